// round 11
// baseline (speedup 1.0000x reference)
#include <cuda_runtime.h>
#include <cuda_bf16.h>
#include <math.h>
#include <stdint.h>

#define BB 4
#define LL 2048
#define DM 512
#define NH 2
#define DK 64
#define HD 128            // NH*DK
#define OUT0 (BB*LL*DM)   // 4194304 floats; attn follows
#define NROWS (BB*NH*LL)  // 16384 attention rows

// scratch (static device globals — no allocations)
__device__ float g_q[BB*LL*HD];
__device__ float g_k[BB*LL*HD];
__device__ float g_v[BB*LL*HD];
__device__ float g_oh[BB*LL*HD];
__device__ float g_rowsum[NROWS];                 // sum exp(s), then lse
__device__ __nv_bfloat16 g_vth[BB*NH*DK*LL];      // vt hi [bh][d][j]
__device__ __nv_bfloat16 g_vtl[BB*NH*DK*LL];      // vt lo [bh][d][j]

__device__ __forceinline__ float fast_tanh(float x) {
    float y;
    asm("tanh.approx.f32 %0, %1;" : "=f"(y) : "f"(x));
    return y;
}

// bf16 HMMA: D(16x8,f32) += A(16x16,bf16 row) * B(16x8,bf16 col)
__device__ __forceinline__ void mma16816(float* d, const uint32_t* a,
                                         const uint32_t* b) {
    asm volatile(
        "mma.sync.aligned.m16n8k16.row.col.f32.bf16.bf16.f32 "
        "{%0,%1,%2,%3}, {%4,%5,%6,%7}, {%8,%9}, {%0,%1,%2,%3};"
        : "+f"(d[0]), "+f"(d[1]), "+f"(d[2]), "+f"(d[3])
        : "r"(a[0]), "r"(a[1]), "r"(a[2]), "r"(a[3]), "r"(b[0]), "r"(b[1]));
}

__device__ __forceinline__ uint32_t bf2pack(float x, float y) {
    __nv_bfloat162 p(__float2bfloat16(x), __float2bfloat16(y));
    return *reinterpret_cast<uint32_t*>(&p);
}

// ---------------------------------------------------------------------------
__global__ __launch_bounds__(256) void zero_rowsum_kernel(float* __restrict__ rs)
{
    rs[blockIdx.x * 256 + threadIdx.x] = 0.0f;
}

__global__ __launch_bounds__(256) void lse_kernel(float* __restrict__ rs)
{
    int i = blockIdx.x * 256 + threadIdx.x;
    rs[i] = logf(rs[i]);
}

// ---------------------------------------------------------------------------
// vt convert: v[b,j,h*64+d] -> vt_hi/lo[bh][d][j] (bf16 hi/lo split)
// grid (LL/128, BB*NH), 256 threads.
// ---------------------------------------------------------------------------
__global__ __launch_bounds__(256) void vt_convert_kernel(
    const float* __restrict__ v,
    __nv_bfloat16* __restrict__ vth, __nv_bfloat16* __restrict__ vtl)
{
    __shared__ float sm[128][68];
    const int bh = blockIdx.y, b = bh >> 1, h = bh & 1;
    const int j0 = blockIdx.x * 128;
    const int tid = threadIdx.x;
#pragma unroll
    for (int r = 0; r < 8; r++) {
        int idx = tid + r * 256;          // 2048 f4 = 128 j x 16 f4
        int j = idx >> 4, d4 = (idx & 15) * 4;
        float4 t = *reinterpret_cast<const float4*>(
            &v[(size_t)(b * LL + j0 + j) * HD + h * DK + d4]);
        *reinterpret_cast<float4*>(&sm[j][d4]) = t;
    }
    __syncthreads();
#pragma unroll
    for (int r = 0; r < 8; r++) {
        int idx = tid + r * 256;          // 2048 quads = 64 d x 32 jq
        int d = idx >> 5, jq = (idx & 31) * 4;
        float x0 = sm[jq + 0][d], x1 = sm[jq + 1][d];
        float x2 = sm[jq + 2][d], x3 = sm[jq + 3][d];
        __nv_bfloat16 h0 = __float2bfloat16(x0), h1 = __float2bfloat16(x1);
        __nv_bfloat16 h2 = __float2bfloat16(x2), h3 = __float2bfloat16(x3);
        uint32_t hp0, hp1, lp0, lp1;
        { __nv_bfloat162 t(h0, h1); hp0 = *(uint32_t*)&t; }
        { __nv_bfloat162 t(h2, h3); hp1 = *(uint32_t*)&t; }
        { __nv_bfloat162 t(__float2bfloat16(x0 - __bfloat162float(h0)),
                           __float2bfloat16(x1 - __bfloat162float(h1))); lp0 = *(uint32_t*)&t; }
        { __nv_bfloat162 t(__float2bfloat16(x2 - __bfloat162float(h2)),
                           __float2bfloat16(x3 - __bfloat162float(h3))); lp1 = *(uint32_t*)&t; }
        size_t off = (size_t)(bh * DK + d) * LL + j0 + jq;
        *reinterpret_cast<uint2*>(&vth[off]) = make_uint2(hp0, hp1);
        *reinterpret_cast<uint2*>(&vtl[off]) = make_uint2(lp0, lp1);
    }
}

// ---------------------------------------------------------------------------
// Tiled GEMM: C[M,N] = A[M,K] @ W[K,N] + bias[N]   (scalar FFMA, proven)
// ---------------------------------------------------------------------------
__device__ __forceinline__ void gemm_core_128x64(
    const float* __restrict__ A, const float* __restrict__ W,
    const float* __restrict__ bias, float* __restrict__ C,
    int N, int K, int bm, int bn, int ldA, int ldC)
{
    __shared__ float As[16][132];
    __shared__ float Ws[16][68];
    const int tid = threadIdx.x;
    const int ty = tid >> 4, tx = tid & 15;
    float acc[8][4] = {};

    for (int k0 = 0; k0 < K; k0 += 16) {
#pragma unroll
        for (int r = 0; r < 2; r++) {
            int idx = tid + r * 256;
            int m = idx >> 2, k4 = idx & 3;
            float4 t = *reinterpret_cast<const float4*>(
                &A[(size_t)(bm + m) * ldA + k0 + k4 * 4]);
            As[k4 * 4 + 0][m] = t.x;
            As[k4 * 4 + 1][m] = t.y;
            As[k4 * 4 + 2][m] = t.z;
            As[k4 * 4 + 3][m] = t.w;
        }
        {
            int kk = tid >> 4, n4 = tid & 15;
            *reinterpret_cast<float4*>(&Ws[kk][n4 * 4]) =
                *reinterpret_cast<const float4*>(
                    &W[(size_t)(k0 + kk) * N + bn + n4 * 4]);
        }
        __syncthreads();
#pragma unroll
        for (int kk = 0; kk < 16; kk++) {
            float4 a0 = *reinterpret_cast<const float4*>(&As[kk][ty * 4]);
            float4 a1 = *reinterpret_cast<const float4*>(&As[kk][64 + ty * 4]);
            float4 b  = *reinterpret_cast<const float4*>(&Ws[kk][tx * 4]);
            float av[8] = {a0.x, a0.y, a0.z, a0.w, a1.x, a1.y, a1.z, a1.w};
            float bv[4] = {b.x, b.y, b.z, b.w};
#pragma unroll
            for (int i = 0; i < 8; i++)
#pragma unroll
                for (int j = 0; j < 4; j++)
                    acc[i][j] += av[i] * bv[j];
        }
        __syncthreads();
    }
    float4 bs = *reinterpret_cast<const float4*>(&bias[bn + tx * 4]);
#pragma unroll
    for (int i = 0; i < 8; i++) {
        int m = bm + ((i < 4) ? (ty * 4 + i) : (64 + ty * 4 + i - 4));
        float4 o = make_float4(acc[i][0] + bs.x, acc[i][1] + bs.y,
                               acc[i][2] + bs.z, acc[i][3] + bs.w);
        *reinterpret_cast<float4*>(&C[(size_t)m * ldC + bn + tx * 4]) = o;
    }
}

__global__ __launch_bounds__(256) void gemm_bias_kernel(
    const float* __restrict__ A, const float* __restrict__ W,
    const float* __restrict__ bias, float* __restrict__ C,
    int M, int N, int K)
{
    gemm_core_128x64(A, W, bias, C, N, K,
                     blockIdx.y * 128, blockIdx.x * 64, K, N);
}

__global__ __launch_bounds__(256) void qkv_kernel(
    const float* __restrict__ Q, const float* __restrict__ K,
    const float* __restrict__ V,
    const float* __restrict__ Wq, const float* __restrict__ Wk,
    const float* __restrict__ Wv,
    const float* __restrict__ bq, const float* __restrict__ bk,
    const float* __restrict__ bv,
    float* __restrict__ q, float* __restrict__ k, float* __restrict__ v)
{
    const float *A, *W, *bias;
    float* C;
    if (blockIdx.z == 0)      { A = Q; W = Wq; bias = bq; C = q; }
    else if (blockIdx.z == 1) { A = K; W = Wk; bias = bk; C = k; }
    else                      { A = V; W = Wv; bias = bv; C = v; }
    gemm_core_128x64(A, W, bias, C, HD, DM,
                     blockIdx.y * 128, blockIdx.x * 64, DM, HD);
}

// ---------------------------------------------------------------------------
// Tensor-core scores via mma.sync bf16 hi/lo split (3 pairings). R8-proven.
// ---------------------------------------------------------------------------
#define SLD 72
#define O_QH 0
#define O_QL (128*SLD)
#define O_KH (2*128*SLD)
#define O_KL (3*128*SLD)
#define SCORES_DYN (4*128*SLD*2)     // 73728 bytes

__global__ __launch_bounds__(256) void scores_mma_kernel(
    const float* __restrict__ q, const float* __restrict__ k,
    const int* __restrict__ mask, float* __restrict__ attn,
    float* __restrict__ rowsum)
{
    extern __shared__ __align__(16) __nv_bfloat16 sm[];
    __shared__ int s_mask[128];

    const int tid = threadIdx.x, wid = tid >> 5, lane = tid & 31;
    const int bh = blockIdx.z, b = bh >> 1, h = bh & 1;
    const int i0 = blockIdx.y * 128, j0 = blockIdx.x * 128;
    const int wm = wid >> 1, wn = wid & 1;

    if (tid < 128) s_mask[tid] = mask[b * LL + j0 + tid];

#pragma unroll
    for (int r = 0; r < 8; r++) {
        int idx = tid + r * 256;
        int m = idx >> 4, d = (idx & 15) * 4;
        {
            float4 t = *reinterpret_cast<const float4*>(
                &q[(size_t)(b * LL + i0 + m) * HD + h * DK + d]);
            __nv_bfloat16 h0 = __float2bfloat16(t.x), h1 = __float2bfloat16(t.y);
            __nv_bfloat16 h2 = __float2bfloat16(t.z), h3 = __float2bfloat16(t.w);
            *reinterpret_cast<uint2*>(&sm[O_QH + m * SLD + d]) = make_uint2(
                bf2pack(t.x, t.y), bf2pack(t.z, t.w));
            *reinterpret_cast<uint2*>(&sm[O_QL + m * SLD + d]) = make_uint2(
                bf2pack(t.x - __bfloat162float(h0), t.y - __bfloat162float(h1)),
                bf2pack(t.z - __bfloat162float(h2), t.w - __bfloat162float(h3)));
        }
        {
            float4 t = *reinterpret_cast<const float4*>(
                &k[(size_t)(b * LL + j0 + m) * HD + h * DK + d]);
            __nv_bfloat16 h0 = __float2bfloat16(t.x), h1 = __float2bfloat16(t.y);
            __nv_bfloat16 h2 = __float2bfloat16(t.z), h3 = __float2bfloat16(t.w);
            *reinterpret_cast<uint2*>(&sm[O_KH + m * SLD + d]) = make_uint2(
                bf2pack(t.x, t.y), bf2pack(t.z, t.w));
            *reinterpret_cast<uint2*>(&sm[O_KL + m * SLD + d]) = make_uint2(
                bf2pack(t.x - __bfloat162float(h0), t.y - __bfloat162float(h1)),
                bf2pack(t.z - __bfloat162float(h2), t.w - __bfloat162float(h3)));
        }
    }
    __syncthreads();

    float acc[2][8][4];
#pragma unroll
    for (int mt = 0; mt < 2; mt++)
#pragma unroll
        for (int nt = 0; nt < 8; nt++)
#pragma unroll
            for (int r = 0; r < 4; r++) acc[mt][nt][r] = 0.0f;

    const int gq = lane >> 2;
    const int qc = (lane & 3) * 2;

#pragma unroll
    for (int ks = 0; ks < 4; ks++) {
        const int kc = ks * 16 + qc;
        uint32_t ah[2][4], al[2][4];
#pragma unroll
        for (int mt = 0; mt < 2; mt++) {
            int gr = wm * 32 + mt * 16 + gq;
            ah[mt][0] = *reinterpret_cast<const uint32_t*>(&sm[O_QH + gr * SLD + kc]);
            ah[mt][1] = *reinterpret_cast<const uint32_t*>(&sm[O_QH + (gr + 8) * SLD + kc]);
            ah[mt][2] = *reinterpret_cast<const uint32_t*>(&sm[O_QH + gr * SLD + kc + 8]);
            ah[mt][3] = *reinterpret_cast<const uint32_t*>(&sm[O_QH + (gr + 8) * SLD + kc + 8]);
            al[mt][0] = *reinterpret_cast<const uint32_t*>(&sm[O_QL + gr * SLD + kc]);
            al[mt][1] = *reinterpret_cast<const uint32_t*>(&sm[O_QL + (gr + 8) * SLD + kc]);
            al[mt][2] = *reinterpret_cast<const uint32_t*>(&sm[O_QL + gr * SLD + kc + 8]);
            al[mt][3] = *reinterpret_cast<const uint32_t*>(&sm[O_QL + (gr + 8) * SLD + kc + 8]);
        }
#pragma unroll
        for (int nt = 0; nt < 8; nt++) {
            int jn = wn * 64 + nt * 8 + gq;
            uint32_t bh2[2], bl2[2];
            bh2[0] = *reinterpret_cast<const uint32_t*>(&sm[O_KH + jn * SLD + kc]);
            bh2[1] = *reinterpret_cast<const uint32_t*>(&sm[O_KH + jn * SLD + kc + 8]);
            bl2[0] = *reinterpret_cast<const uint32_t*>(&sm[O_KL + jn * SLD + kc]);
            bl2[1] = *reinterpret_cast<const uint32_t*>(&sm[O_KL + jn * SLD + kc + 8]);
#pragma unroll
            for (int mt = 0; mt < 2; mt++) {
                mma16816(acc[mt][nt], ah[mt], bh2);
                mma16816(acc[mt][nt], al[mt], bh2);
                mma16816(acc[mt][nt], ah[mt], bl2);
            }
        }
    }

#pragma unroll
    for (int mt = 0; mt < 2; mt++) {
        int r0 = wm * 32 + mt * 16 + gq;
        int r1 = r0 + 8;
        float rs0 = 0.0f, rs1 = 0.0f;
#pragma unroll
        for (int nt = 0; nt < 8; nt++) {
            int c = wn * 64 + nt * 8 + (lane & 3) * 2;
            int mk0 = s_mask[c], mk1 = s_mask[c + 1];
            float w0 = mk0 ? -10.0f : fast_tanh(acc[mt][nt][0] * 0.125f) * 10.0f;
            float w1 = mk1 ? -10.0f : fast_tanh(acc[mt][nt][1] * 0.125f) * 10.0f;
            float w2 = mk0 ? -10.0f : fast_tanh(acc[mt][nt][2] * 0.125f) * 10.0f;
            float w3 = mk1 ? -10.0f : fast_tanh(acc[mt][nt][3] * 0.125f) * 10.0f;
            *reinterpret_cast<float2*>(
                &attn[((size_t)bh * LL + i0 + r0) * LL + j0 + c]) = make_float2(w0, w1);
            *reinterpret_cast<float2*>(
                &attn[((size_t)bh * LL + i0 + r1) * LL + j0 + c]) = make_float2(w2, w3);
            rs0 += __expf(w0) + __expf(w1);
            rs1 += __expf(w2) + __expf(w3);
        }
        rs0 += __shfl_xor_sync(0xffffffffu, rs0, 1);
        rs0 += __shfl_xor_sync(0xffffffffu, rs0, 2);
        rs1 += __shfl_xor_sync(0xffffffffu, rs1, 1);
        rs1 += __shfl_xor_sync(0xffffffffu, rs1, 2);
        if ((lane & 3) == 0) {
            atomicAdd(&rowsum[bh * LL + i0 + r0], rs0);
            atomicAdd(&rowsum[bh * LL + i0 + r1], rs1);
        }
    }
}

// ---------------------------------------------------------------------------
// av via mma.sync: w = attn - lse (written back), oh = w @ v.
// 128(i) x 64(d) tile; 8 warps, each m16 x n64 (8 subtiles); j chunks of 64.
// A = w bf16 hi/lo (smem), B = vt bf16 hi/lo [d][j] (global pre-transposed).
// ---------------------------------------------------------------------------
#define A_H 0
#define A_L (128*SLD)
#define B_H (2*128*SLD)
#define B_L (2*128*SLD + 64*SLD)
#define AV_DYN ((2*128*SLD + 2*64*SLD)*2 + 512)   // bf16 tiles + lse

__global__ __launch_bounds__(256) void av_mma_kernel(
    float* __restrict__ attn,
    const __nv_bfloat16* __restrict__ vth, const __nv_bfloat16* __restrict__ vtl,
    const float* __restrict__ lse, float* __restrict__ oh)
{
    extern __shared__ __align__(16) __nv_bfloat16 sm[];
    float* lse_s = reinterpret_cast<float*>(sm + 2*128*SLD + 2*64*SLD);

    const int tid = threadIdx.x, wid = tid >> 5, lane = tid & 31;
    const int bh = blockIdx.y, b = bh >> 1, h = bh & 1;
    const int i0 = blockIdx.x * 128;
    const int gq = lane >> 2, qc = (lane & 3) * 2;

    if (tid < 128) lse_s[tid] = lse[bh * LL + i0 + tid];
    __syncthreads();

    float acc[8][4];
#pragma unroll
    for (int nt = 0; nt < 8; nt++)
#pragma unroll
        for (int r = 0; r < 4; r++) acc[nt][r] = 0.0f;

    for (int k0 = 0; k0 < LL; k0 += 64) {
        // attn chunk 128 x 64: subtract lse, write back, stage hi/lo
#pragma unroll
        for (int r = 0; r < 8; r++) {
            int idx = tid + r * 256;          // 2048 f4
            int i = idx >> 4, j4 = (idx & 15) * 4;
            float* gp = &attn[((size_t)bh * LL + i0 + i) * LL + k0 + j4];
            float4 t = *reinterpret_cast<const float4*>(gp);
            float l = lse_s[i];
            t.x -= l; t.y -= l; t.z -= l; t.w -= l;
            *reinterpret_cast<float4*>(gp) = t;
            __nv_bfloat16 h0 = __float2bfloat16(t.x), h1 = __float2bfloat16(t.y);
            __nv_bfloat16 h2 = __float2bfloat16(t.z), h3 = __float2bfloat16(t.w);
            *reinterpret_cast<uint2*>(&sm[A_H + i * SLD + j4]) = make_uint2(
                bf2pack(t.x, t.y), bf2pack(t.z, t.w));
            *reinterpret_cast<uint2*>(&sm[A_L + i * SLD + j4]) = make_uint2(
                bf2pack(t.x - __bfloat162float(h0), t.y - __bfloat162float(h1)),
                bf2pack(t.z - __bfloat162float(h2), t.w - __bfloat162float(h3)));
        }
        // vt chunk 64(d) x 64(j), hi+lo
#pragma unroll
        for (int r = 0; r < 2; r++) {
            int idx = tid + r * 256;          // 512 uint4 = 64 d x 8 u4
            int d = idx >> 3, j8 = (idx & 7) * 8;
            size_t off = (size_t)(bh * DK + d) * LL + k0 + j8;
            *reinterpret_cast<uint4*>(&sm[B_H + d * SLD + j8]) =
                *reinterpret_cast<const uint4*>(&vth[off]);
            *reinterpret_cast<uint4*>(&sm[B_L + d * SLD + j8]) =
                *reinterpret_cast<const uint4*>(&vtl[off]);
        }
        __syncthreads();

#pragma unroll
        for (int ks = 0; ks < 4; ks++) {
            const int kc = ks * 16 + qc;
            int gr = wid * 16 + gq;
            uint32_t ah[4], al[4];
            ah[0] = *reinterpret_cast<const uint32_t*>(&sm[A_H + gr * SLD + kc]);
            ah[1] = *reinterpret_cast<const uint32_t*>(&sm[A_H + (gr + 8) * SLD + kc]);
            ah[2] = *reinterpret_cast<const uint32_t*>(&sm[A_H + gr * SLD + kc + 8]);
            ah[3] = *reinterpret_cast<const uint32_t*>(&sm[A_H + (gr + 8) * SLD + kc + 8]);
            al[0] = *reinterpret_cast<const uint32_t*>(&sm[A_L + gr * SLD + kc]);
            al[1] = *reinterpret_cast<const uint32_t*>(&sm[A_L + (gr + 8) * SLD + kc]);
            al[2] = *reinterpret_cast<const uint32_t*>(&sm[A_L + gr * SLD + kc + 8]);
            al[3] = *reinterpret_cast<const uint32_t*>(&sm[A_L + (gr + 8) * SLD + kc + 8]);
#pragma unroll
            for (int nt = 0; nt < 8; nt++) {
                int dn = nt * 8 + gq;
                uint32_t bh2[2], bl2[2];
                bh2[0] = *reinterpret_cast<const uint32_t*>(&sm[B_H + dn * SLD + kc]);
                bh2[1] = *reinterpret_cast<const uint32_t*>(&sm[B_H + dn * SLD + kc + 8]);
                bl2[0] = *reinterpret_cast<const uint32_t*>(&sm[B_L + dn * SLD + kc]);
                bl2[1] = *reinterpret_cast<const uint32_t*>(&sm[B_L + dn * SLD + kc + 8]);
                mma16816(acc[nt], ah, bh2);
                mma16816(acc[nt], al, bh2);
                mma16816(acc[nt], ah, bl2);
            }
        }
        __syncthreads();
    }

    // epilogue: oh[i0 + wid*16 + gq(+8)][d]
    int r0 = i0 + wid * 16 + gq;
    int r1 = r0 + 8;
#pragma unroll
    for (int nt = 0; nt < 8; nt++) {
        int c = nt * 8 + (lane & 3) * 2;
        *reinterpret_cast<float2*>(
            &oh[(size_t)(b * LL + r0) * HD + h * DK + c]) =
            make_float2(acc[nt][0], acc[nt][1]);
        *reinterpret_cast<float2*>(
            &oh[(size_t)(b * LL + r1) * HD + h * DK + c]) =
            make_float2(acc[nt][2], acc[nt][3]);
    }
}

// ---------------------------------------------------------------------------
extern "C" void kernel_launch(void* const* d_in, const int* in_sizes, int n_in,
                              void* d_out, int out_size)
{
    const float* Q  = (const float*)d_in[0];
    const float* K  = (const float*)d_in[1];
    const float* V  = (const float*)d_in[2];
    const int*   mask = (const int*)d_in[3];
    const float* Wq = (const float*)d_in[4];
    const float* bq = (const float*)d_in[5];
    const float* Wk = (const float*)d_in[6];
    const float* bk = (const float*)d_in[7];
    const float* Wv = (const float*)d_in[8];
    const float* bv = (const float*)d_in[9];
    const float* Wo = (const float*)d_in[10];
    const float* bo = (const float*)d_in[11];

    float* out  = (float*)d_out;          // [B, Lq, 512]
    float* attn = out + OUT0;             // [B, H, Lq, Lk]

    float *q, *k, *v, *oh, *rs;
    __nv_bfloat16 *vth, *vtl;
    cudaGetSymbolAddress((void**)&q,  g_q);
    cudaGetSymbolAddress((void**)&k,  g_k);
    cudaGetSymbolAddress((void**)&v,  g_v);
    cudaGetSymbolAddress((void**)&oh, g_oh);
    cudaGetSymbolAddress((void**)&rs, g_rowsum);
    cudaGetSymbolAddress((void**)&vth, g_vth);
    cudaGetSymbolAddress((void**)&vtl, g_vtl);

    const int M = BB * LL;                // 8192
    cudaFuncSetAttribute(scores_mma_kernel,
                         cudaFuncAttributeMaxDynamicSharedMemorySize, SCORES_DYN);
    cudaFuncSetAttribute(av_mma_kernel,
                         cudaFuncAttributeMaxDynamicSharedMemorySize, AV_DYN);

    // 0) zero the rowsum accumulator
    zero_rowsum_kernel<<<NROWS / 256, 256>>>(rs);

    // 1) fused projections: [8192,512] @ [512,128] x3
    dim3 gp(HD / 64, M / 128, 3);
    qkv_kernel<<<gp, 256>>>(Q, K, V, Wq, Wk, Wv, bq, bk, bv, q, k, v);

    // 1b) transpose+split v -> vt (bf16 hi/lo)
    dim3 gv(LL / 128, BB * NH);
    vt_convert_kernel<<<gv, 256>>>(v, vth, vtl);

    // 2) tensor-core scores + tanh clip + mask -> attn (raw) + rowsum atomics
    dim3 gs(LL / 128, LL / 128, BB * NH);
    scores_mma_kernel<<<gs, 256, SCORES_DYN>>>(q, k, mask, attn, rs);

    // 3) rowsum -> lse
    lse_kernel<<<NROWS / 256, 256>>>(rs);

    // 4) attn = s - lse (written back) ; oh = attn @ v (tensor)
    dim3 ga(LL / 128, BB * NH);
    av_mma_kernel<<<ga, 256, AV_DYN>>>(attn, vth, vtl, rs, oh);

    // 5) out = oh @ Wo + bo : [8192,128] @ [128,512]
    dim3 go(DM / 64, M / 128);
    gemm_bias_kernel<<<go, 256>>>(oh, Wo, bo, out, M, DM, HD);
}

// round 13
// speedup vs baseline: 1.0048x; 1.0048x over previous
#include <cuda_runtime.h>
#include <cuda_bf16.h>
#include <math.h>
#include <stdint.h>

#define BB 4
#define LL 2048
#define DM 512
#define NH 2
#define DK 64
#define HD 128            // NH*DK
#define OUT0 (BB*LL*DM)   // 4194304 floats; attn follows
#define NROWS (BB*NH*LL)  // 16384 attention rows

// scratch (static device globals — no allocations)
__device__ float g_q[BB*LL*HD];
__device__ float g_k[BB*LL*HD];
__device__ float g_v[BB*LL*HD];
__device__ float g_oh[BB*LL*HD];
__device__ float g_rowsum[NROWS];                 // sum exp(s), then lse
__device__ __nv_bfloat16 g_qh[BB*LL*HD];          // q hi  (same layout as g_q)
__device__ __nv_bfloat16 g_ql[BB*LL*HD];          // q lo
__device__ __nv_bfloat16 g_kh[BB*LL*HD];          // k hi
__device__ __nv_bfloat16 g_kl[BB*LL*HD];          // k lo
__device__ __nv_bfloat16 g_vth[BB*NH*DK*LL];      // vt hi [bh][d][j]
__device__ __nv_bfloat16 g_vtl[BB*NH*DK*LL];      // vt lo [bh][d][j]

__device__ __forceinline__ float fast_tanh(float x) {
    float y;
    asm("tanh.approx.f32 %0, %1;" : "=f"(y) : "f"(x));
    return y;
}

// bf16 HMMA: D(16x8,f32) += A(16x16,bf16 row) * B(16x8,bf16 col)
__device__ __forceinline__ void mma16816(float* d, const uint32_t* a,
                                         const uint32_t* b) {
    asm volatile(
        "mma.sync.aligned.m16n8k16.row.col.f32.bf16.bf16.f32 "
        "{%0,%1,%2,%3}, {%4,%5,%6,%7}, {%8,%9}, {%0,%1,%2,%3};"
        : "+f"(d[0]), "+f"(d[1]), "+f"(d[2]), "+f"(d[3])
        : "r"(a[0]), "r"(a[1]), "r"(a[2]), "r"(a[3]), "r"(b[0]), "r"(b[1]));
}

// packed f32 pair -> bf16x2 (lo half = x, hi half = y), RN
__device__ __forceinline__ uint32_t cvt_bf16x2(float x, float y) {
    uint32_t r;
    asm("cvt.rn.bf16x2.f32 %0, %1, %2;" : "=r"(r) : "f"(y), "f"(x));
    return r;
}
// exact bf16x2 -> f32 pair
__device__ __forceinline__ float2 bf16x2_f32(uint32_t u) {
    return make_float2(__uint_as_float(u << 16),
                       __uint_as_float(u & 0xffff0000u));
}
// split f4 into hi/lo bf16x2 pairs (fast path)
__device__ __forceinline__ void split4(float4 t, uint32_t& h0, uint32_t& h1,
                                       uint32_t& l0, uint32_t& l1) {
    h0 = cvt_bf16x2(t.x, t.y);
    h1 = cvt_bf16x2(t.z, t.w);
    float2 a0 = bf16x2_f32(h0), a1 = bf16x2_f32(h1);
    l0 = cvt_bf16x2(t.x - a0.x, t.y - a0.y);
    l1 = cvt_bf16x2(t.z - a1.x, t.w - a1.y);
}

// ---------------------------------------------------------------------------
__global__ __launch_bounds__(256) void zero_rowsum_kernel(float* __restrict__ rs)
{
    rs[blockIdx.x * 256 + threadIdx.x] = 0.0f;
}

__global__ __launch_bounds__(256) void lse_kernel(float* __restrict__ rs)
{
    int i = blockIdx.x * 256 + threadIdx.x;
    rs[i] = logf(rs[i]);
}

// ---------------------------------------------------------------------------
// vt convert: v[b,j,h*64+d] -> vt_hi/lo[bh][d][j]
// ---------------------------------------------------------------------------
__global__ __launch_bounds__(256) void vt_convert_kernel(
    const float* __restrict__ v,
    __nv_bfloat16* __restrict__ vth, __nv_bfloat16* __restrict__ vtl)
{
    __shared__ float sm[128][68];
    const int bh = blockIdx.y, b = bh >> 1, h = bh & 1;
    const int j0 = blockIdx.x * 128;
    const int tid = threadIdx.x;
#pragma unroll
    for (int r = 0; r < 8; r++) {
        int idx = tid + r * 256;
        int j = idx >> 4, d4 = (idx & 15) * 4;
        float4 t = *reinterpret_cast<const float4*>(
            &v[(size_t)(b * LL + j0 + j) * HD + h * DK + d4]);
        *reinterpret_cast<float4*>(&sm[j][d4]) = t;
    }
    __syncthreads();
#pragma unroll
    for (int r = 0; r < 8; r++) {
        int idx = tid + r * 256;
        int d = idx >> 5, jq = (idx & 31) * 4;
        float4 t = make_float4(sm[jq + 0][d], sm[jq + 1][d],
                               sm[jq + 2][d], sm[jq + 3][d]);
        uint32_t h0, h1, l0, l1;
        split4(t, h0, h1, l0, l1);
        size_t off = (size_t)(bh * DK + d) * LL + j0 + jq;
        *reinterpret_cast<uint2*>(&vth[off]) = make_uint2(h0, h1);
        *reinterpret_cast<uint2*>(&vtl[off]) = make_uint2(l0, l1);
    }
}

// ---------------------------------------------------------------------------
// Tiled GEMM: C[M,N] = A[M,K] @ W[K,N] + bias[N]   (scalar FFMA, proven)
// If Chi/Clo non-null, also emit bf16 hi/lo copies of C.
// ---------------------------------------------------------------------------
__device__ __forceinline__ void gemm_core_128x64(
    const float* __restrict__ A, const float* __restrict__ W,
    const float* __restrict__ bias, float* __restrict__ C,
    int N, int K, int bm, int bn, int ldA, int ldC,
    __nv_bfloat16* __restrict__ Chi, __nv_bfloat16* __restrict__ Clo)
{
    __shared__ float As[16][132];
    __shared__ float Ws[16][68];
    const int tid = threadIdx.x;
    const int ty = tid >> 4, tx = tid & 15;
    float acc[8][4] = {};

    for (int k0 = 0; k0 < K; k0 += 16) {
#pragma unroll
        for (int r = 0; r < 2; r++) {
            int idx = tid + r * 256;
            int m = idx >> 2, k4 = idx & 3;
            float4 t = *reinterpret_cast<const float4*>(
                &A[(size_t)(bm + m) * ldA + k0 + k4 * 4]);
            As[k4 * 4 + 0][m] = t.x;
            As[k4 * 4 + 1][m] = t.y;
            As[k4 * 4 + 2][m] = t.z;
            As[k4 * 4 + 3][m] = t.w;
        }
        {
            int kk = tid >> 4, n4 = tid & 15;
            *reinterpret_cast<float4*>(&Ws[kk][n4 * 4]) =
                *reinterpret_cast<const float4*>(
                    &W[(size_t)(k0 + kk) * N + bn + n4 * 4]);
        }
        __syncthreads();
#pragma unroll
        for (int kk = 0; kk < 16; kk++) {
            float4 a0 = *reinterpret_cast<const float4*>(&As[kk][ty * 4]);
            float4 a1 = *reinterpret_cast<const float4*>(&As[kk][64 + ty * 4]);
            float4 b  = *reinterpret_cast<const float4*>(&Ws[kk][tx * 4]);
            float av[8] = {a0.x, a0.y, a0.z, a0.w, a1.x, a1.y, a1.z, a1.w};
            float bv[4] = {b.x, b.y, b.z, b.w};
#pragma unroll
            for (int i = 0; i < 8; i++)
#pragma unroll
                for (int j = 0; j < 4; j++)
                    acc[i][j] += av[i] * bv[j];
        }
        __syncthreads();
    }
    float4 bs = *reinterpret_cast<const float4*>(&bias[bn + tx * 4]);
#pragma unroll
    for (int i = 0; i < 8; i++) {
        int m = bm + ((i < 4) ? (ty * 4 + i) : (64 + ty * 4 + i - 4));
        float4 o = make_float4(acc[i][0] + bs.x, acc[i][1] + bs.y,
                               acc[i][2] + bs.z, acc[i][3] + bs.w);
        size_t off = (size_t)m * ldC + bn + tx * 4;
        *reinterpret_cast<float4*>(&C[off]) = o;
        if (Chi) {
            uint32_t h0, h1, l0, l1;
            split4(o, h0, h1, l0, l1);
            *reinterpret_cast<uint2*>(&Chi[off]) = make_uint2(h0, h1);
            *reinterpret_cast<uint2*>(&Clo[off]) = make_uint2(l0, l1);
        }
    }
}

__global__ __launch_bounds__(256) void gemm_bias_kernel(
    const float* __restrict__ A, const float* __restrict__ W,
    const float* __restrict__ bias, float* __restrict__ C,
    int M, int N, int K)
{
    gemm_core_128x64(A, W, bias, C, N, K,
                     blockIdx.y * 128, blockIdx.x * 64, K, N, nullptr, nullptr);
}

__global__ __launch_bounds__(256) void qkv_kernel(
    const float* __restrict__ Q, const float* __restrict__ K,
    const float* __restrict__ V,
    const float* __restrict__ Wq, const float* __restrict__ Wk,
    const float* __restrict__ Wv,
    const float* __restrict__ bq, const float* __restrict__ bk,
    const float* __restrict__ bv,
    float* __restrict__ q, float* __restrict__ k, float* __restrict__ v,
    __nv_bfloat16* __restrict__ qh, __nv_bfloat16* __restrict__ ql,
    __nv_bfloat16* __restrict__ kh, __nv_bfloat16* __restrict__ kl)
{
    const float *A, *W, *bias;
    float* C;
    __nv_bfloat16 *Chi = nullptr, *Clo = nullptr;
    if (blockIdx.z == 0)      { A = Q; W = Wq; bias = bq; C = q; Chi = qh; Clo = ql; }
    else if (blockIdx.z == 1) { A = K; W = Wk; bias = bk; C = k; Chi = kh; Clo = kl; }
    else                      { A = V; W = Wv; bias = bv; C = v; }
    gemm_core_128x64(A, W, bias, C, HD, DM,
                     blockIdx.y * 128, blockIdx.x * 64, DM, HD, Chi, Clo);
}

// ---------------------------------------------------------------------------
// Tensor-core scores via mma.sync bf16 hi/lo (3 pairings), pre-split inputs.
// ---------------------------------------------------------------------------
#define SLD 72
#define O_QH 0
#define O_QL (128*SLD)
#define O_KH (2*128*SLD)
#define O_KL (3*128*SLD)
#define SCORES_DYN (4*128*SLD*2)     // 73728 bytes

__global__ __launch_bounds__(256) void scores_mma_kernel(
    const __nv_bfloat16* __restrict__ qh, const __nv_bfloat16* __restrict__ ql,
    const __nv_bfloat16* __restrict__ kh, const __nv_bfloat16* __restrict__ kl,
    const int* __restrict__ mask, float* __restrict__ attn,
    float* __restrict__ rowsum)
{
    extern __shared__ __align__(16) __nv_bfloat16 sm[];
    __shared__ int s_mask[128];

    const int tid = threadIdx.x, wid = tid >> 5, lane = tid & 31;
    const int bh = blockIdx.z, b = bh >> 1, h = bh & 1;
    const int i0 = blockIdx.y * 128, j0 = blockIdx.x * 128;
    const int wm = wid >> 1, wn = wid & 1;

    if (tid < 128) s_mask[tid] = mask[b * LL + j0 + tid];

    // stage pre-split bf16 tiles: 4 buffers x 128 rows x 64 = 1024 uint4 each
#pragma unroll
    for (int r = 0; r < 4; r++) {
        int idx = tid + r * 256;          // 1024 = 128 rows x 8 u4
        int m = idx >> 3, d8 = (idx & 7) * 8;
        size_t qoff = (size_t)(b * LL + i0 + m) * HD + h * DK + d8;
        size_t koff = (size_t)(b * LL + j0 + m) * HD + h * DK + d8;
        *reinterpret_cast<uint4*>(&sm[O_QH + m * SLD + d8]) =
            *reinterpret_cast<const uint4*>(&qh[qoff]);
        *reinterpret_cast<uint4*>(&sm[O_QL + m * SLD + d8]) =
            *reinterpret_cast<const uint4*>(&ql[qoff]);
        *reinterpret_cast<uint4*>(&sm[O_KH + m * SLD + d8]) =
            *reinterpret_cast<const uint4*>(&kh[koff]);
        *reinterpret_cast<uint4*>(&sm[O_KL + m * SLD + d8]) =
            *reinterpret_cast<const uint4*>(&kl[koff]);
    }
    __syncthreads();

    float acc[2][8][4];
#pragma unroll
    for (int mt = 0; mt < 2; mt++)
#pragma unroll
        for (int nt = 0; nt < 8; nt++)
#pragma unroll
            for (int r = 0; r < 4; r++) acc[mt][nt][r] = 0.0f;

    const int gq = lane >> 2;
    const int qc = (lane & 3) * 2;

#pragma unroll
    for (int ks = 0; ks < 4; ks++) {
        const int kc = ks * 16 + qc;
        uint32_t ah[2][4], al[2][4];
#pragma unroll
        for (int mt = 0; mt < 2; mt++) {
            int gr = wm * 32 + mt * 16 + gq;
            ah[mt][0] = *reinterpret_cast<const uint32_t*>(&sm[O_QH + gr * SLD + kc]);
            ah[mt][1] = *reinterpret_cast<const uint32_t*>(&sm[O_QH + (gr + 8) * SLD + kc]);
            ah[mt][2] = *reinterpret_cast<const uint32_t*>(&sm[O_QH + gr * SLD + kc + 8]);
            ah[mt][3] = *reinterpret_cast<const uint32_t*>(&sm[O_QH + (gr + 8) * SLD + kc + 8]);
            al[mt][0] = *reinterpret_cast<const uint32_t*>(&sm[O_QL + gr * SLD + kc]);
            al[mt][1] = *reinterpret_cast<const uint32_t*>(&sm[O_QL + (gr + 8) * SLD + kc]);
            al[mt][2] = *reinterpret_cast<const uint32_t*>(&sm[O_QL + gr * SLD + kc + 8]);
            al[mt][3] = *reinterpret_cast<const uint32_t*>(&sm[O_QL + (gr + 8) * SLD + kc + 8]);
        }
#pragma unroll
        for (int nt = 0; nt < 8; nt++) {
            int jn = wn * 64 + nt * 8 + gq;
            uint32_t bh2[2], bl2[2];
            bh2[0] = *reinterpret_cast<const uint32_t*>(&sm[O_KH + jn * SLD + kc]);
            bh2[1] = *reinterpret_cast<const uint32_t*>(&sm[O_KH + jn * SLD + kc + 8]);
            bl2[0] = *reinterpret_cast<const uint32_t*>(&sm[O_KL + jn * SLD + kc]);
            bl2[1] = *reinterpret_cast<const uint32_t*>(&sm[O_KL + jn * SLD + kc + 8]);
#pragma unroll
            for (int mt = 0; mt < 2; mt++) {
                mma16816(acc[mt][nt], ah[mt], bh2);
                mma16816(acc[mt][nt], al[mt], bh2);
                mma16816(acc[mt][nt], ah[mt], bl2);
            }
        }
    }

#pragma unroll
    for (int mt = 0; mt < 2; mt++) {
        int r0 = wm * 32 + mt * 16 + gq;
        int r1 = r0 + 8;
        float rs0 = 0.0f, rs1 = 0.0f;
#pragma unroll
        for (int nt = 0; nt < 8; nt++) {
            int c = wn * 64 + nt * 8 + (lane & 3) * 2;
            int mk0 = s_mask[c], mk1 = s_mask[c + 1];
            float w0 = mk0 ? -10.0f : fast_tanh(acc[mt][nt][0] * 0.125f) * 10.0f;
            float w1 = mk1 ? -10.0f : fast_tanh(acc[mt][nt][1] * 0.125f) * 10.0f;
            float w2 = mk0 ? -10.0f : fast_tanh(acc[mt][nt][2] * 0.125f) * 10.0f;
            float w3 = mk1 ? -10.0f : fast_tanh(acc[mt][nt][3] * 0.125f) * 10.0f;
            *reinterpret_cast<float2*>(
                &attn[((size_t)bh * LL + i0 + r0) * LL + j0 + c]) = make_float2(w0, w1);
            *reinterpret_cast<float2*>(
                &attn[((size_t)bh * LL + i0 + r1) * LL + j0 + c]) = make_float2(w2, w3);
            rs0 += __expf(w0) + __expf(w1);
            rs1 += __expf(w2) + __expf(w3);
        }
        rs0 += __shfl_xor_sync(0xffffffffu, rs0, 1);
        rs0 += __shfl_xor_sync(0xffffffffu, rs0, 2);
        rs1 += __shfl_xor_sync(0xffffffffu, rs1, 1);
        rs1 += __shfl_xor_sync(0xffffffffu, rs1, 2);
        if ((lane & 3) == 0) {
            atomicAdd(&rowsum[bh * LL + i0 + r0], rs0);
            atomicAdd(&rowsum[bh * LL + i0 + r1], rs1);
        }
    }
}

// ---------------------------------------------------------------------------
// av via mma.sync: w = attn - lse (written back), oh = w @ v.
// 128(i) x 64(d) tile; 8 warps, each m16 x n64; j chunks of 64. Fast split.
// ---------------------------------------------------------------------------
#define A_H 0
#define A_L (128*SLD)
#define B_H (2*128*SLD)
#define B_L (2*128*SLD + 64*SLD)
#define AV_DYN ((2*128*SLD + 2*64*SLD)*2 + 512)

__global__ __launch_bounds__(256) void av_mma_kernel(
    float* __restrict__ attn,
    const __nv_bfloat16* __restrict__ vth, const __nv_bfloat16* __restrict__ vtl,
    const float* __restrict__ lse, float* __restrict__ oh)
{
    extern __shared__ __align__(16) __nv_bfloat16 sm[];
    float* lse_s = reinterpret_cast<float*>(sm + 2*128*SLD + 2*64*SLD);

    const int tid = threadIdx.x, wid = tid >> 5, lane = tid & 31;
    const int bh = blockIdx.y, b = bh >> 1, h = bh & 1;
    const int i0 = blockIdx.x * 128;
    const int gq = lane >> 2, qc = (lane & 3) * 2;

    if (tid < 128) lse_s[tid] = lse[bh * LL + i0 + tid];
    __syncthreads();

    float acc[8][4];
#pragma unroll
    for (int nt = 0; nt < 8; nt++)
#pragma unroll
        for (int r = 0; r < 4; r++) acc[nt][r] = 0.0f;

    for (int k0 = 0; k0 < LL; k0 += 64) {
#pragma unroll
        for (int r = 0; r < 8; r++) {
            int idx = tid + r * 256;
            int i = idx >> 4, j4 = (idx & 15) * 4;
            float* gp = &attn[((size_t)bh * LL + i0 + i) * LL + k0 + j4];
            float4 t = *reinterpret_cast<const float4*>(gp);
            float l = lse_s[i];
            t.x -= l; t.y -= l; t.z -= l; t.w -= l;
            *reinterpret_cast<float4*>(gp) = t;
            uint32_t h0, h1, l0, l1;
            split4(t, h0, h1, l0, l1);
            *reinterpret_cast<uint2*>(&sm[A_H + i * SLD + j4]) = make_uint2(h0, h1);
            *reinterpret_cast<uint2*>(&sm[A_L + i * SLD + j4]) = make_uint2(l0, l1);
        }
#pragma unroll
        for (int r = 0; r < 2; r++) {
            int idx = tid + r * 256;
            int d = idx >> 3, j8 = (idx & 7) * 8;
            size_t off = (size_t)(bh * DK + d) * LL + k0 + j8;
            *reinterpret_cast<uint4*>(&sm[B_H + d * SLD + j8]) =
                *reinterpret_cast<const uint4*>(&vth[off]);
            *reinterpret_cast<uint4*>(&sm[B_L + d * SLD + j8]) =
                *reinterpret_cast<const uint4*>(&vtl[off]);
        }
        __syncthreads();

#pragma unroll
        for (int ks = 0; ks < 4; ks++) {
            const int kc = ks * 16 + qc;
            int gr = wid * 16 + gq;
            uint32_t ah[4], al[4];
            ah[0] = *reinterpret_cast<const uint32_t*>(&sm[A_H + gr * SLD + kc]);
            ah[1] = *reinterpret_cast<const uint32_t*>(&sm[A_H + (gr + 8) * SLD + kc]);
            ah[2] = *reinterpret_cast<const uint32_t*>(&sm[A_H + gr * SLD + kc + 8]);
            ah[3] = *reinterpret_cast<const uint32_t*>(&sm[A_H + (gr + 8) * SLD + kc + 8]);
            al[0] = *reinterpret_cast<const uint32_t*>(&sm[A_L + gr * SLD + kc]);
            al[1] = *reinterpret_cast<const uint32_t*>(&sm[A_L + (gr + 8) * SLD + kc]);
            al[2] = *reinterpret_cast<const uint32_t*>(&sm[A_L + gr * SLD + kc + 8]);
            al[3] = *reinterpret_cast<const uint32_t*>(&sm[A_L + (gr + 8) * SLD + kc + 8]);
#pragma unroll
            for (int nt = 0; nt < 8; nt++) {
                int dn = nt * 8 + gq;
                uint32_t bh2[2], bl2[2];
                bh2[0] = *reinterpret_cast<const uint32_t*>(&sm[B_H + dn * SLD + kc]);
                bh2[1] = *reinterpret_cast<const uint32_t*>(&sm[B_H + dn * SLD + kc + 8]);
                bl2[0] = *reinterpret_cast<const uint32_t*>(&sm[B_L + dn * SLD + kc]);
                bl2[1] = *reinterpret_cast<const uint32_t*>(&sm[B_L + dn * SLD + kc + 8]);
                mma16816(acc[nt], ah, bh2);
                mma16816(acc[nt], al, bh2);
                mma16816(acc[nt], ah, bl2);
            }
        }
        __syncthreads();
    }

    int r0 = i0 + wid * 16 + gq;
    int r1 = r0 + 8;
#pragma unroll
    for (int nt = 0; nt < 8; nt++) {
        int c = nt * 8 + (lane & 3) * 2;
        *reinterpret_cast<float2*>(
            &oh[(size_t)(b * LL + r0) * HD + h * DK + c]) =
            make_float2(acc[nt][0], acc[nt][1]);
        *reinterpret_cast<float2*>(
            &oh[(size_t)(b * LL + r1) * HD + h * DK + c]) =
            make_float2(acc[nt][2], acc[nt][3]);
    }
}

// ---------------------------------------------------------------------------
extern "C" void kernel_launch(void* const* d_in, const int* in_sizes, int n_in,
                              void* d_out, int out_size)
{
    const float* Q  = (const float*)d_in[0];
    const float* K  = (const float*)d_in[1];
    const float* V  = (const float*)d_in[2];
    const int*   mask = (const int*)d_in[3];
    const float* Wq = (const float*)d_in[4];
    const float* bq = (const float*)d_in[5];
    const float* Wk = (const float*)d_in[6];
    const float* bk = (const float*)d_in[7];
    const float* Wv = (const float*)d_in[8];
    const float* bv = (const float*)d_in[9];
    const float* Wo = (const float*)d_in[10];
    const float* bo = (const float*)d_in[11];

    float* out  = (float*)d_out;          // [B, Lq, 512]
    float* attn = out + OUT0;             // [B, H, Lq, Lk]

    float *q, *k, *v, *oh, *rs;
    __nv_bfloat16 *qh, *ql, *kh, *kl, *vth, *vtl;
    cudaGetSymbolAddress((void**)&q,  g_q);
    cudaGetSymbolAddress((void**)&k,  g_k);
    cudaGetSymbolAddress((void**)&v,  g_v);
    cudaGetSymbolAddress((void**)&oh, g_oh);
    cudaGetSymbolAddress((void**)&rs, g_rowsum);
    cudaGetSymbolAddress((void**)&qh, g_qh);
    cudaGetSymbolAddress((void**)&ql, g_ql);
    cudaGetSymbolAddress((void**)&kh, g_kh);
    cudaGetSymbolAddress((void**)&kl, g_kl);
    cudaGetSymbolAddress((void**)&vth, g_vth);
    cudaGetSymbolAddress((void**)&vtl, g_vtl);

    const int M = BB * LL;                // 8192
    cudaFuncSetAttribute(scores_mma_kernel,
                         cudaFuncAttributeMaxDynamicSharedMemorySize, SCORES_DYN);
    cudaFuncSetAttribute(av_mma_kernel,
                         cudaFuncAttributeMaxDynamicSharedMemorySize, AV_DYN);

    // 0) zero the rowsum accumulator
    zero_rowsum_kernel<<<NROWS / 256, 256>>>(rs);

    // 1) fused projections (+ bf16 hi/lo emission for q,k)
    dim3 gp(HD / 64, M / 128, 3);
    qkv_kernel<<<gp, 256>>>(Q, K, V, Wq, Wk, Wv, bq, bk, bv,
                            q, k, v, qh, ql, kh, kl);

    // 1b) transpose+split v -> vt (bf16 hi/lo)
    dim3 gv(LL / 128, BB * NH);
    vt_convert_kernel<<<gv, 256>>>(v, vth, vtl);

    // 2) tensor-core scores + tanh clip + mask -> attn (raw) + rowsum atomics
    dim3 gs(LL / 128, LL / 128, BB * NH);
    scores_mma_kernel<<<gs, 256, SCORES_DYN>>>(qh, ql, kh, kl, mask, attn, rs);

    // 3) rowsum -> lse
    lse_kernel<<<NROWS / 256, 256>>>(rs);

    // 4) attn = s - lse (written back) ; oh = attn @ v (tensor)
    dim3 ga(LL / 128, BB * NH);
    av_mma_kernel<<<ga, 256, AV_DYN>>>(attn, vth, vtl, rs, oh);

    // 5) out = oh @ Wo + bo : [8192,128] @ [128,512]
    dim3 go(DM / 64, M / 128);
    gemm_bias_kernel<<<go, 256>>>(oh, Wo, bo, out, M, DM, HD);
}

// round 15
// speedup vs baseline: 1.4237x; 1.4169x over previous
#include <cuda_runtime.h>
#include <cuda_bf16.h>
#include <math.h>
#include <stdint.h>

#define BB 4
#define LL 2048
#define DM 512
#define NH 2
#define DK 64
#define HD 128            // NH*DK
#define OUT0 (BB*LL*DM)   // 4194304 floats; attn follows
#define NROWS (BB*NH*LL)  // 16384 attention rows

// scratch (static device globals — no allocations)
__device__ float g_q[BB*LL*HD];
__device__ float g_k[BB*LL*HD];
__device__ float g_v[BB*LL*HD];
__device__ float g_oh[BB*LL*HD];
__device__ float g_rowsum[NROWS];                 // sum exp(s), then lse
__device__ __nv_bfloat16 g_qh[BB*LL*HD];          // q hi  (same layout as g_q)
__device__ __nv_bfloat16 g_ql[BB*LL*HD];          // q lo
__device__ __nv_bfloat16 g_kh[BB*LL*HD];          // k hi
__device__ __nv_bfloat16 g_kl[BB*LL*HD];          // k lo
__device__ __nv_bfloat16 g_vth[BB*NH*DK*LL];      // vt hi [bh][d][j]
__device__ __nv_bfloat16 g_vtl[BB*NH*DK*LL];      // vt lo [bh][d][j]

__device__ __forceinline__ float fast_tanh(float x) {
    float y;
    asm("tanh.approx.f32 %0, %1;" : "=f"(y) : "f"(x));
    return y;
}

// bf16 HMMA: D(16x8,f32) += A(16x16,bf16 row) * B(16x8,bf16 col)
__device__ __forceinline__ void mma16816(float* d, const uint32_t* a,
                                         const uint32_t* b) {
    asm volatile(
        "mma.sync.aligned.m16n8k16.row.col.f32.bf16.bf16.f32 "
        "{%0,%1,%2,%3}, {%4,%5,%6,%7}, {%8,%9}, {%0,%1,%2,%3};"
        : "+f"(d[0]), "+f"(d[1]), "+f"(d[2]), "+f"(d[3])
        : "r"(a[0]), "r"(a[1]), "r"(a[2]), "r"(a[3]), "r"(b[0]), "r"(b[1]));
}

// packed f32 pair -> bf16x2 (lo half = x, hi half = y), RN
__device__ __forceinline__ uint32_t cvt_bf16x2(float x, float y) {
    uint32_t r;
    asm("cvt.rn.bf16x2.f32 %0, %1, %2;" : "=r"(r) : "f"(y), "f"(x));
    return r;
}
// exact bf16x2 -> f32 pair
__device__ __forceinline__ float2 bf16x2_f32(uint32_t u) {
    return make_float2(__uint_as_float(u << 16),
                       __uint_as_float(u & 0xffff0000u));
}
// split f4 into hi/lo bf16x2 pairs
__device__ __forceinline__ void split4(float4 t, uint32_t& h0, uint32_t& h1,
                                       uint32_t& l0, uint32_t& l1) {
    h0 = cvt_bf16x2(t.x, t.y);
    h1 = cvt_bf16x2(t.z, t.w);
    float2 a0 = bf16x2_f32(h0), a1 = bf16x2_f32(h1);
    l0 = cvt_bf16x2(t.x - a0.x, t.y - a0.y);
    l1 = cvt_bf16x2(t.z - a1.x, t.w - a1.y);
}

// XOR-swizzled element offset inside a [rows][64] bf16 tile (128B rows,
// 8x 16B blocks per row, block index XORed with row&7 -> conflict-free
// fragment LDS and aligned uint2/uint4 STS).
__device__ __forceinline__ int SWZ(int row, int e) {
    return row * 64 + ((((e) >> 3) ^ (row & 7)) << 3) + ((e) & 7);
}

// ---------------------------------------------------------------------------
__global__ __launch_bounds__(256) void zero_rowsum_kernel(float* __restrict__ rs)
{
    rs[blockIdx.x * 256 + threadIdx.x] = 0.0f;
}

__global__ __launch_bounds__(256) void lse_kernel(float* __restrict__ rs)
{
    int i = blockIdx.x * 256 + threadIdx.x;
    rs[i] = logf(rs[i]);
}

// ---------------------------------------------------------------------------
// vt convert: v[b,j,h*64+d] -> vt_hi/lo[bh][d][j]
// ---------------------------------------------------------------------------
__global__ __launch_bounds__(256) void vt_convert_kernel(
    const float* __restrict__ v,
    __nv_bfloat16* __restrict__ vth, __nv_bfloat16* __restrict__ vtl)
{
    __shared__ float sm[128][68];
    const int bh = blockIdx.y, b = bh >> 1, h = bh & 1;
    const int j0 = blockIdx.x * 128;
    const int tid = threadIdx.x;
#pragma unroll
    for (int r = 0; r < 8; r++) {
        int idx = tid + r * 256;
        int j = idx >> 4, d4 = (idx & 15) * 4;
        float4 t = *reinterpret_cast<const float4*>(
            &v[(size_t)(b * LL + j0 + j) * HD + h * DK + d4]);
        *reinterpret_cast<float4*>(&sm[j][d4]) = t;
    }
    __syncthreads();
#pragma unroll
    for (int r = 0; r < 8; r++) {
        int idx = tid + r * 256;
        int d = idx >> 5, jq = (idx & 31) * 4;
        float4 t = make_float4(sm[jq + 0][d], sm[jq + 1][d],
                               sm[jq + 2][d], sm[jq + 3][d]);
        uint32_t h0, h1, l0, l1;
        split4(t, h0, h1, l0, l1);
        size_t off = (size_t)(bh * DK + d) * LL + j0 + jq;
        *reinterpret_cast<uint2*>(&vth[off]) = make_uint2(h0, h1);
        *reinterpret_cast<uint2*>(&vtl[off]) = make_uint2(l0, l1);
    }
}

// ---------------------------------------------------------------------------
// Tiled GEMM: C[M,N] = A[M,K] @ W[K,N] + bias[N]   (scalar FFMA, proven)
// If Chi/Clo non-null, also emit bf16 hi/lo copies of C.
// ---------------------------------------------------------------------------
__device__ __forceinline__ void gemm_core_128x64(
    const float* __restrict__ A, const float* __restrict__ W,
    const float* __restrict__ bias, float* __restrict__ C,
    int N, int K, int bm, int bn, int ldA, int ldC,
    __nv_bfloat16* __restrict__ Chi, __nv_bfloat16* __restrict__ Clo)
{
    __shared__ float As[16][132];
    __shared__ float Ws[16][68];
    const int tid = threadIdx.x;
    const int ty = tid >> 4, tx = tid & 15;
    float acc[8][4] = {};

    for (int k0 = 0; k0 < K; k0 += 16) {
#pragma unroll
        for (int r = 0; r < 2; r++) {
            int idx = tid + r * 256;
            int m = idx >> 2, k4 = idx & 3;
            float4 t = *reinterpret_cast<const float4*>(
                &A[(size_t)(bm + m) * ldA + k0 + k4 * 4]);
            As[k4 * 4 + 0][m] = t.x;
            As[k4 * 4 + 1][m] = t.y;
            As[k4 * 4 + 2][m] = t.z;
            As[k4 * 4 + 3][m] = t.w;
        }
        {
            int kk = tid >> 4, n4 = tid & 15;
            *reinterpret_cast<float4*>(&Ws[kk][n4 * 4]) =
                *reinterpret_cast<const float4*>(
                    &W[(size_t)(k0 + kk) * N + bn + n4 * 4]);
        }
        __syncthreads();
#pragma unroll
        for (int kk = 0; kk < 16; kk++) {
            float4 a0 = *reinterpret_cast<const float4*>(&As[kk][ty * 4]);
            float4 a1 = *reinterpret_cast<const float4*>(&As[kk][64 + ty * 4]);
            float4 b  = *reinterpret_cast<const float4*>(&Ws[kk][tx * 4]);
            float av[8] = {a0.x, a0.y, a0.z, a0.w, a1.x, a1.y, a1.z, a1.w};
            float bv[4] = {b.x, b.y, b.z, b.w};
#pragma unroll
            for (int i = 0; i < 8; i++)
#pragma unroll
                for (int j = 0; j < 4; j++)
                    acc[i][j] += av[i] * bv[j];
        }
        __syncthreads();
    }
    float4 bs = *reinterpret_cast<const float4*>(&bias[bn + tx * 4]);
#pragma unroll
    for (int i = 0; i < 8; i++) {
        int m = bm + ((i < 4) ? (ty * 4 + i) : (64 + ty * 4 + i - 4));
        float4 o = make_float4(acc[i][0] + bs.x, acc[i][1] + bs.y,
                               acc[i][2] + bs.z, acc[i][3] + bs.w);
        size_t off = (size_t)m * ldC + bn + tx * 4;
        *reinterpret_cast<float4*>(&C[off]) = o;
        if (Chi) {
            uint32_t h0, h1, l0, l1;
            split4(o, h0, h1, l0, l1);
            *reinterpret_cast<uint2*>(&Chi[off]) = make_uint2(h0, h1);
            *reinterpret_cast<uint2*>(&Clo[off]) = make_uint2(l0, l1);
        }
    }
}

__global__ __launch_bounds__(256) void gemm_bias_kernel(
    const float* __restrict__ A, const float* __restrict__ W,
    const float* __restrict__ bias, float* __restrict__ C,
    int M, int N, int K)
{
    gemm_core_128x64(A, W, bias, C, N, K,
                     blockIdx.y * 128, blockIdx.x * 64, K, N, nullptr, nullptr);
}

__global__ __launch_bounds__(256) void qkv_kernel(
    const float* __restrict__ Q, const float* __restrict__ K,
    const float* __restrict__ V,
    const float* __restrict__ Wq, const float* __restrict__ Wk,
    const float* __restrict__ Wv,
    const float* __restrict__ bq, const float* __restrict__ bk,
    const float* __restrict__ bv,
    float* __restrict__ q, float* __restrict__ k, float* __restrict__ v,
    __nv_bfloat16* __restrict__ qh, __nv_bfloat16* __restrict__ ql,
    __nv_bfloat16* __restrict__ kh, __nv_bfloat16* __restrict__ kl)
{
    const float *A, *W, *bias;
    float* C;
    __nv_bfloat16 *Chi = nullptr, *Clo = nullptr;
    if (blockIdx.z == 0)      { A = Q; W = Wq; bias = bq; C = q; Chi = qh; Clo = ql; }
    else if (blockIdx.z == 1) { A = K; W = Wk; bias = bk; C = k; Chi = kh; Clo = kl; }
    else                      { A = V; W = Wv; bias = bv; C = v; }
    gemm_core_128x64(A, W, bias, C, HD, DM,
                     blockIdx.y * 128, blockIdx.x * 64, DM, HD, Chi, Clo);
}

// ---------------------------------------------------------------------------
// Tensor-core scores via mma.sync bf16 hi/lo (3 pairings), pre-split inputs,
// XOR-swizzled smem (conflict-free fragment LDS).
// ---------------------------------------------------------------------------
#define O_QH 0
#define O_QL (128*64)
#define O_KH (2*128*64)
#define O_KL (3*128*64)
#define SCORES_DYN (4*128*64*2)      // 65536 bytes

__global__ __launch_bounds__(256) void scores_mma_kernel(
    const __nv_bfloat16* __restrict__ qh, const __nv_bfloat16* __restrict__ ql,
    const __nv_bfloat16* __restrict__ kh, const __nv_bfloat16* __restrict__ kl,
    const int* __restrict__ mask, float* __restrict__ attn,
    float* __restrict__ rowsum)
{
    extern __shared__ __align__(16) __nv_bfloat16 sm[];
    __shared__ int s_mask[128];

    const int tid = threadIdx.x, wid = tid >> 5, lane = tid & 31;
    const int bh = blockIdx.z, b = bh >> 1, h = bh & 1;
    const int i0 = blockIdx.y * 128, j0 = blockIdx.x * 128;
    const int wm = wid >> 1, wn = wid & 1;

    if (tid < 128) s_mask[tid] = mask[b * LL + j0 + tid];

    // stage pre-split bf16 tiles (swizzled): 4 buffers x 128 rows x 64
#pragma unroll
    for (int r = 0; r < 4; r++) {
        int idx = tid + r * 256;          // 1024 = 128 rows x 8 u4
        int m = idx >> 3, d8 = (idx & 7) * 8;
        int so = SWZ(m, d8);
        size_t qoff = (size_t)(b * LL + i0 + m) * HD + h * DK + d8;
        size_t koff = (size_t)(b * LL + j0 + m) * HD + h * DK + d8;
        *reinterpret_cast<uint4*>(&sm[O_QH + so]) =
            *reinterpret_cast<const uint4*>(&qh[qoff]);
        *reinterpret_cast<uint4*>(&sm[O_QL + so]) =
            *reinterpret_cast<const uint4*>(&ql[qoff]);
        *reinterpret_cast<uint4*>(&sm[O_KH + so]) =
            *reinterpret_cast<const uint4*>(&kh[koff]);
        *reinterpret_cast<uint4*>(&sm[O_KL + so]) =
            *reinterpret_cast<const uint4*>(&kl[koff]);
    }
    __syncthreads();

    float acc[2][8][4];
#pragma unroll
    for (int mt = 0; mt < 2; mt++)
#pragma unroll
        for (int nt = 0; nt < 8; nt++)
#pragma unroll
            for (int r = 0; r < 4; r++) acc[mt][nt][r] = 0.0f;

    const int gq = lane >> 2;
    const int qc = (lane & 3) * 2;

#pragma unroll
    for (int ks = 0; ks < 4; ks++) {
        const int kc = ks * 16 + qc;
        uint32_t ah[2][4], al[2][4];
#pragma unroll
        for (int mt = 0; mt < 2; mt++) {
            int gr = wm * 32 + mt * 16 + gq;
            ah[mt][0] = *reinterpret_cast<const uint32_t*>(&sm[O_QH + SWZ(gr, kc)]);
            ah[mt][1] = *reinterpret_cast<const uint32_t*>(&sm[O_QH + SWZ(gr + 8, kc)]);
            ah[mt][2] = *reinterpret_cast<const uint32_t*>(&sm[O_QH + SWZ(gr, kc + 8)]);
            ah[mt][3] = *reinterpret_cast<const uint32_t*>(&sm[O_QH + SWZ(gr + 8, kc + 8)]);
            al[mt][0] = *reinterpret_cast<const uint32_t*>(&sm[O_QL + SWZ(gr, kc)]);
            al[mt][1] = *reinterpret_cast<const uint32_t*>(&sm[O_QL + SWZ(gr + 8, kc)]);
            al[mt][2] = *reinterpret_cast<const uint32_t*>(&sm[O_QL + SWZ(gr, kc + 8)]);
            al[mt][3] = *reinterpret_cast<const uint32_t*>(&sm[O_QL + SWZ(gr + 8, kc + 8)]);
        }
#pragma unroll
        for (int nt = 0; nt < 8; nt++) {
            int jn = wn * 64 + nt * 8 + gq;
            uint32_t bh2[2], bl2[2];
            bh2[0] = *reinterpret_cast<const uint32_t*>(&sm[O_KH + SWZ(jn, kc)]);
            bh2[1] = *reinterpret_cast<const uint32_t*>(&sm[O_KH + SWZ(jn, kc + 8)]);
            bl2[0] = *reinterpret_cast<const uint32_t*>(&sm[O_KL + SWZ(jn, kc)]);
            bl2[1] = *reinterpret_cast<const uint32_t*>(&sm[O_KL + SWZ(jn, kc + 8)]);
#pragma unroll
            for (int mt = 0; mt < 2; mt++) {
                mma16816(acc[mt][nt], ah[mt], bh2);
                mma16816(acc[mt][nt], al[mt], bh2);
                mma16816(acc[mt][nt], ah[mt], bl2);
            }
        }
    }

#pragma unroll
    for (int mt = 0; mt < 2; mt++) {
        int r0 = wm * 32 + mt * 16 + gq;
        int r1 = r0 + 8;
        float rs0 = 0.0f, rs1 = 0.0f;
#pragma unroll
        for (int nt = 0; nt < 8; nt++) {
            int c = wn * 64 + nt * 8 + (lane & 3) * 2;
            int mk0 = s_mask[c], mk1 = s_mask[c + 1];
            float w0 = mk0 ? -10.0f : fast_tanh(acc[mt][nt][0] * 0.125f) * 10.0f;
            float w1 = mk1 ? -10.0f : fast_tanh(acc[mt][nt][1] * 0.125f) * 10.0f;
            float w2 = mk0 ? -10.0f : fast_tanh(acc[mt][nt][2] * 0.125f) * 10.0f;
            float w3 = mk1 ? -10.0f : fast_tanh(acc[mt][nt][3] * 0.125f) * 10.0f;
            *reinterpret_cast<float2*>(
                &attn[((size_t)bh * LL + i0 + r0) * LL + j0 + c]) = make_float2(w0, w1);
            *reinterpret_cast<float2*>(
                &attn[((size_t)bh * LL + i0 + r1) * LL + j0 + c]) = make_float2(w2, w3);
            rs0 += __expf(w0) + __expf(w1);
            rs1 += __expf(w2) + __expf(w3);
        }
        rs0 += __shfl_xor_sync(0xffffffffu, rs0, 1);
        rs0 += __shfl_xor_sync(0xffffffffu, rs0, 2);
        rs1 += __shfl_xor_sync(0xffffffffu, rs1, 1);
        rs1 += __shfl_xor_sync(0xffffffffu, rs1, 2);
        if ((lane & 3) == 0) {
            atomicAdd(&rowsum[bh * LL + i0 + r0], rs0);
            atomicAdd(&rowsum[bh * LL + i0 + r1], rs1);
        }
    }
}

// ---------------------------------------------------------------------------
// av via mma.sync, double-buffered + register-prefetch pipeline.
// w = attn - lse (written back), oh = w @ v.
// 128(i) x 64(d) tile; 8 warps m16 x n64; j chunks of 64; swizzled smem.
// Stage layout (elements, per buffer): AH 0..8191, AL 8192.., BH 16384..,
// BL 20480..; stage stride 24576. lse at element 49152.
// ---------------------------------------------------------------------------
#define AV_STAGE 24576
#define AV_AH 0
#define AV_AL 8192
#define AV_BH 16384
#define AV_BL 20480
#define AV_DYN (2*AV_STAGE*2 + 512)

__global__ __launch_bounds__(256) void av_mma_kernel(
    float* __restrict__ attn,
    const __nv_bfloat16* __restrict__ vth, const __nv_bfloat16* __restrict__ vtl,
    const float* __restrict__ lse, float* __restrict__ oh)
{
    extern __shared__ __align__(16) __nv_bfloat16 sm[];
    float* lse_s = reinterpret_cast<float*>(sm + 2 * AV_STAGE);

    const int tid = threadIdx.x, wid = tid >> 5, lane = tid & 31;
    const int bh = blockIdx.y, b = bh >> 1, h = bh & 1;
    const int i0 = blockIdx.x * 128;
    const int gq = lane >> 2, qc = (lane & 3) * 2;

    if (tid < 128) lse_s[tid] = lse[bh * LL + i0 + tid];
    __syncthreads();

    float acc[8][4];
#pragma unroll
    for (int nt = 0; nt < 8; nt++)
#pragma unroll
        for (int r = 0; r < 4; r++) acc[nt][r] = 0.0f;

    float4 pa[8];
    uint4  pbh[2], pbl[2];

    // prefetch-issue (global -> regs)
    auto issue_loads = [&](int k0) {
#pragma unroll
        for (int r = 0; r < 8; r++) {
            int idx = tid + r * 256;
            int i = idx >> 4, j4 = (idx & 15) * 4;
            pa[r] = *reinterpret_cast<const float4*>(
                &attn[((size_t)bh * LL + i0 + i) * LL + k0 + j4]);
        }
#pragma unroll
        for (int r = 0; r < 2; r++) {
            int idx = tid + r * 256;
            int d = idx >> 3, j8 = (idx & 7) * 8;
            size_t off = (size_t)(bh * DK + d) * LL + k0 + j8;
            pbh[r] = *reinterpret_cast<const uint4*>(&vth[off]);
            pbl[r] = *reinterpret_cast<const uint4*>(&vtl[off]);
        }
    };
    // regs -> (lse-subtract, attn writeback, bf16 split) -> smem stage
    auto convert_store = [&](int k0, int buf) {
        int base = buf * AV_STAGE;
#pragma unroll
        for (int r = 0; r < 8; r++) {
            int idx = tid + r * 256;
            int i = idx >> 4, j4 = (idx & 15) * 4;
            float4 t = pa[r];
            float l = lse_s[i];
            t.x -= l; t.y -= l; t.z -= l; t.w -= l;
            *reinterpret_cast<float4*>(
                &attn[((size_t)bh * LL + i0 + i) * LL + k0 + j4]) = t;
            uint32_t h0, h1, l0, l1;
            split4(t, h0, h1, l0, l1);
            int so = SWZ(i, j4);
            *reinterpret_cast<uint2*>(&sm[base + AV_AH + so]) = make_uint2(h0, h1);
            *reinterpret_cast<uint2*>(&sm[base + AV_AL + so]) = make_uint2(l0, l1);
        }
#pragma unroll
        for (int r = 0; r < 2; r++) {
            int idx = tid + r * 256;
            int d = idx >> 3, j8 = (idx & 7) * 8;
            int so = SWZ(d, j8);
            *reinterpret_cast<uint4*>(&sm[base + AV_BH + so]) = pbh[r];
            *reinterpret_cast<uint4*>(&sm[base + AV_BL + so]) = pbl[r];
        }
    };

    issue_loads(0);
    convert_store(0, 0);
    __syncthreads();

    for (int t = 0; t < 32; t++) {
        int buf = t & 1;
        int base = buf * AV_STAGE;
        if (t < 31) issue_loads((t + 1) * 64);

#pragma unroll
        for (int ks = 0; ks < 4; ks++) {
            const int kc = ks * 16 + qc;
            int gr = wid * 16 + gq;
            uint32_t ah[4], al[4];
            ah[0] = *reinterpret_cast<const uint32_t*>(&sm[base + AV_AH + SWZ(gr, kc)]);
            ah[1] = *reinterpret_cast<const uint32_t*>(&sm[base + AV_AH + SWZ(gr + 8, kc)]);
            ah[2] = *reinterpret_cast<const uint32_t*>(&sm[base + AV_AH + SWZ(gr, kc + 8)]);
            ah[3] = *reinterpret_cast<const uint32_t*>(&sm[base + AV_AH + SWZ(gr + 8, kc + 8)]);
            al[0] = *reinterpret_cast<const uint32_t*>(&sm[base + AV_AL + SWZ(gr, kc)]);
            al[1] = *reinterpret_cast<const uint32_t*>(&sm[base + AV_AL + SWZ(gr + 8, kc)]);
            al[2] = *reinterpret_cast<const uint32_t*>(&sm[base + AV_AL + SWZ(gr, kc + 8)]);
            al[3] = *reinterpret_cast<const uint32_t*>(&sm[base + AV_AL + SWZ(gr + 8, kc + 8)]);
#pragma unroll
            for (int nt = 0; nt < 8; nt++) {
                int dn = nt * 8 + gq;
                uint32_t bh2[2], bl2[2];
                bh2[0] = *reinterpret_cast<const uint32_t*>(&sm[base + AV_BH + SWZ(dn, kc)]);
                bh2[1] = *reinterpret_cast<const uint32_t*>(&sm[base + AV_BH + SWZ(dn, kc + 8)]);
                bl2[0] = *reinterpret_cast<const uint32_t*>(&sm[base + AV_BL + SWZ(dn, kc)]);
                bl2[1] = *reinterpret_cast<const uint32_t*>(&sm[base + AV_BL + SWZ(dn, kc + 8)]);
                mma16816(acc[nt], ah, bh2);
                mma16816(acc[nt], al, bh2);
                mma16816(acc[nt], ah, bl2);
            }
        }

        if (t < 31) convert_store((t + 1) * 64, 1 - buf);
        __syncthreads();
    }

    int r0 = i0 + wid * 16 + gq;
    int r1 = r0 + 8;
#pragma unroll
    for (int nt = 0; nt < 8; nt++) {
        int c = nt * 8 + (lane & 3) * 2;
        *reinterpret_cast<float2*>(
            &oh[(size_t)(b * LL + r0) * HD + h * DK + c]) =
            make_float2(acc[nt][0], acc[nt][1]);
        *reinterpret_cast<float2*>(
            &oh[(size_t)(b * LL + r1) * HD + h * DK + c]) =
            make_float2(acc[nt][2], acc[nt][3]);
    }
}

// ---------------------------------------------------------------------------
extern "C" void kernel_launch(void* const* d_in, const int* in_sizes, int n_in,
                              void* d_out, int out_size)
{
    const float* Q  = (const float*)d_in[0];
    const float* K  = (const float*)d_in[1];
    const float* V  = (const float*)d_in[2];
    const int*   mask = (const int*)d_in[3];
    const float* Wq = (const float*)d_in[4];
    const float* bq = (const float*)d_in[5];
    const float* Wk = (const float*)d_in[6];
    const float* bk = (const float*)d_in[7];
    const float* Wv = (const float*)d_in[8];
    const float* bv = (const float*)d_in[9];
    const float* Wo = (const float*)d_in[10];
    const float* bo = (const float*)d_in[11];

    float* out  = (float*)d_out;          // [B, Lq, 512]
    float* attn = out + OUT0;             // [B, H, Lq, Lk]

    float *q, *k, *v, *oh, *rs;
    __nv_bfloat16 *qh, *ql, *kh, *kl, *vth, *vtl;
    cudaGetSymbolAddress((void**)&q,  g_q);
    cudaGetSymbolAddress((void**)&k,  g_k);
    cudaGetSymbolAddress((void**)&v,  g_v);
    cudaGetSymbolAddress((void**)&oh, g_oh);
    cudaGetSymbolAddress((void**)&rs, g_rowsum);
    cudaGetSymbolAddress((void**)&qh, g_qh);
    cudaGetSymbolAddress((void**)&ql, g_ql);
    cudaGetSymbolAddress((void**)&kh, g_kh);
    cudaGetSymbolAddress((void**)&kl, g_kl);
    cudaGetSymbolAddress((void**)&vth, g_vth);
    cudaGetSymbolAddress((void**)&vtl, g_vtl);

    const int M = BB * LL;                // 8192
    cudaFuncSetAttribute(scores_mma_kernel,
                         cudaFuncAttributeMaxDynamicSharedMemorySize, SCORES_DYN);
    cudaFuncSetAttribute(av_mma_kernel,
                         cudaFuncAttributeMaxDynamicSharedMemorySize, AV_DYN);

    // 0) zero the rowsum accumulator
    zero_rowsum_kernel<<<NROWS / 256, 256>>>(rs);

    // 1) fused projections (+ bf16 hi/lo emission for q,k)
    dim3 gp(HD / 64, M / 128, 3);
    qkv_kernel<<<gp, 256>>>(Q, K, V, Wq, Wk, Wv, bq, bk, bv,
                            q, k, v, qh, ql, kh, kl);

    // 1b) transpose+split v -> vt (bf16 hi/lo)
    dim3 gv(LL / 128, BB * NH);
    vt_convert_kernel<<<gv, 256>>>(v, vth, vtl);

    // 2) tensor-core scores + tanh clip + mask -> attn (raw) + rowsum atomics
    dim3 gs(LL / 128, LL / 128, BB * NH);
    scores_mma_kernel<<<gs, 256, SCORES_DYN>>>(qh, ql, kh, kl, mask, attn, rs);

    // 3) rowsum -> lse
    lse_kernel<<<NROWS / 256, 256>>>(rs);

    // 4) attn = s - lse (written back) ; oh = attn @ v (tensor, pipelined)
    dim3 ga(LL / 128, BB * NH);
    av_mma_kernel<<<ga, 256, AV_DYN>>>(attn, vth, vtl, rs, oh);

    // 5) out = oh @ Wo + bo : [8192,128] @ [128,512]
    dim3 go(DM / 64, M / 128);
    gemm_bias_kernel<<<go, 256>>>(oh, Wo, bo, out, M, DM, HD);
}

// round 16
// speedup vs baseline: 1.4921x; 1.0481x over previous
#include <cuda_runtime.h>
#include <cuda_bf16.h>
#include <math.h>
#include <stdint.h>

#define BB 4
#define LL 2048
#define DM 512
#define NH 2
#define DK 64
#define HD 128            // NH*DK
#define OUT0 (BB*LL*DM)   // 4194304 floats; attn follows
#define NROWS (BB*NH*LL)  // 16384 attention rows

// scratch (static device globals — no allocations)
__device__ float g_q[BB*LL*HD];
__device__ float g_k[BB*LL*HD];
__device__ float g_v[BB*LL*HD];
__device__ float g_oh[BB*LL*HD];
__device__ float g_rowsum[NROWS];                 // sum exp(s), then lse
__device__ __nv_bfloat16 g_qh[BB*LL*HD];          // q hi  (same layout as g_q)
__device__ __nv_bfloat16 g_ql[BB*LL*HD];          // q lo
__device__ __nv_bfloat16 g_kh[BB*LL*HD];          // k hi
__device__ __nv_bfloat16 g_kl[BB*LL*HD];          // k lo
__device__ __nv_bfloat16 g_vth[BB*NH*DK*LL];      // vt hi [bh][d][j]
__device__ __nv_bfloat16 g_vtl[BB*NH*DK*LL];      // vt lo [bh][d][j]

__device__ __forceinline__ float fast_tanh(float x) {
    float y;
    asm("tanh.approx.f32 %0, %1;" : "=f"(y) : "f"(x));
    return y;
}

// bf16 HMMA: D(16x8,f32) += A(16x16,bf16 row) * B(16x8,bf16 col)
__device__ __forceinline__ void mma16816(float* d, const uint32_t* a,
                                         const uint32_t* b) {
    asm volatile(
        "mma.sync.aligned.m16n8k16.row.col.f32.bf16.bf16.f32 "
        "{%0,%1,%2,%3}, {%4,%5,%6,%7}, {%8,%9}, {%0,%1,%2,%3};"
        : "+f"(d[0]), "+f"(d[1]), "+f"(d[2]), "+f"(d[3])
        : "r"(a[0]), "r"(a[1]), "r"(a[2]), "r"(a[3]), "r"(b[0]), "r"(b[1]));
}

// packed f32 pair -> bf16x2 (lo half = x, hi half = y), RN
__device__ __forceinline__ uint32_t cvt_bf16x2(float x, float y) {
    uint32_t r;
    asm("cvt.rn.bf16x2.f32 %0, %1, %2;" : "=r"(r) : "f"(y), "f"(x));
    return r;
}
// exact bf16x2 -> f32 pair
__device__ __forceinline__ float2 bf16x2_f32(uint32_t u) {
    return make_float2(__uint_as_float(u << 16),
                       __uint_as_float(u & 0xffff0000u));
}
// split f4 into hi/lo bf16x2 pairs
__device__ __forceinline__ void split4(float4 t, uint32_t& h0, uint32_t& h1,
                                       uint32_t& l0, uint32_t& l1) {
    h0 = cvt_bf16x2(t.x, t.y);
    h1 = cvt_bf16x2(t.z, t.w);
    float2 a0 = bf16x2_f32(h0), a1 = bf16x2_f32(h1);
    l0 = cvt_bf16x2(t.x - a0.x, t.y - a0.y);
    l1 = cvt_bf16x2(t.z - a1.x, t.w - a1.y);
}

// XOR-swizzled element offset inside a [rows][64] bf16 tile (128B rows,
// 8x 16B blocks per row, block index XORed with row&7 -> conflict-free
// fragment LDS and aligned uint2/uint4 STS).
__device__ __forceinline__ int SWZ(int row, int e) {
    return row * 64 + ((((e) >> 3) ^ (row & 7)) << 3) + ((e) & 7);
}

// ---------------------------------------------------------------------------
__global__ __launch_bounds__(256) void zero_rowsum_kernel(float* __restrict__ rs)
{
    rs[blockIdx.x * 256 + threadIdx.x] = 0.0f;
}

__global__ __launch_bounds__(256) void lse_kernel(float* __restrict__ rs)
{
    int i = blockIdx.x * 256 + threadIdx.x;
    rs[i] = logf(rs[i]);
}

// ---------------------------------------------------------------------------
// vt convert: v[b,j,h*64+d] -> vt_hi/lo[bh][d][j]
// ---------------------------------------------------------------------------
__global__ __launch_bounds__(256) void vt_convert_kernel(
    const float* __restrict__ v,
    __nv_bfloat16* __restrict__ vth, __nv_bfloat16* __restrict__ vtl)
{
    __shared__ float sm[128][68];
    const int bh = blockIdx.y, b = bh >> 1, h = bh & 1;
    const int j0 = blockIdx.x * 128;
    const int tid = threadIdx.x;
#pragma unroll
    for (int r = 0; r < 8; r++) {
        int idx = tid + r * 256;
        int j = idx >> 4, d4 = (idx & 15) * 4;
        float4 t = *reinterpret_cast<const float4*>(
            &v[(size_t)(b * LL + j0 + j) * HD + h * DK + d4]);
        *reinterpret_cast<float4*>(&sm[j][d4]) = t;
    }
    __syncthreads();
#pragma unroll
    for (int r = 0; r < 8; r++) {
        int idx = tid + r * 256;
        int d = idx >> 5, jq = (idx & 31) * 4;
        float4 t = make_float4(sm[jq + 0][d], sm[jq + 1][d],
                               sm[jq + 2][d], sm[jq + 3][d]);
        uint32_t h0, h1, l0, l1;
        split4(t, h0, h1, l0, l1);
        size_t off = (size_t)(bh * DK + d) * LL + j0 + jq;
        *reinterpret_cast<uint2*>(&vth[off]) = make_uint2(h0, h1);
        *reinterpret_cast<uint2*>(&vtl[off]) = make_uint2(l0, l1);
    }
}

// ---------------------------------------------------------------------------
// Tiled GEMM: C[M,N] = A[M,K] @ W[K,N] + bias[N]   (scalar FFMA, proven)
// If Chi/Clo non-null, also emit bf16 hi/lo copies of C.
// ---------------------------------------------------------------------------
__device__ __forceinline__ void gemm_core_128x64(
    const float* __restrict__ A, const float* __restrict__ W,
    const float* __restrict__ bias, float* __restrict__ C,
    int N, int K, int bm, int bn, int ldA, int ldC,
    __nv_bfloat16* __restrict__ Chi, __nv_bfloat16* __restrict__ Clo)
{
    __shared__ float As[16][132];
    __shared__ float Ws[16][68];
    const int tid = threadIdx.x;
    const int ty = tid >> 4, tx = tid & 15;
    float acc[8][4] = {};

    for (int k0 = 0; k0 < K; k0 += 16) {
#pragma unroll
        for (int r = 0; r < 2; r++) {
            int idx = tid + r * 256;
            int m = idx >> 2, k4 = idx & 3;
            float4 t = *reinterpret_cast<const float4*>(
                &A[(size_t)(bm + m) * ldA + k0 + k4 * 4]);
            As[k4 * 4 + 0][m] = t.x;
            As[k4 * 4 + 1][m] = t.y;
            As[k4 * 4 + 2][m] = t.z;
            As[k4 * 4 + 3][m] = t.w;
        }
        {
            int kk = tid >> 4, n4 = tid & 15;
            *reinterpret_cast<float4*>(&Ws[kk][n4 * 4]) =
                *reinterpret_cast<const float4*>(
                    &W[(size_t)(k0 + kk) * N + bn + n4 * 4]);
        }
        __syncthreads();
#pragma unroll
        for (int kk = 0; kk < 16; kk++) {
            float4 a0 = *reinterpret_cast<const float4*>(&As[kk][ty * 4]);
            float4 a1 = *reinterpret_cast<const float4*>(&As[kk][64 + ty * 4]);
            float4 b  = *reinterpret_cast<const float4*>(&Ws[kk][tx * 4]);
            float av[8] = {a0.x, a0.y, a0.z, a0.w, a1.x, a1.y, a1.z, a1.w};
            float bv[4] = {b.x, b.y, b.z, b.w};
#pragma unroll
            for (int i = 0; i < 8; i++)
#pragma unroll
                for (int j = 0; j < 4; j++)
                    acc[i][j] += av[i] * bv[j];
        }
        __syncthreads();
    }
    float4 bs = *reinterpret_cast<const float4*>(&bias[bn + tx * 4]);
#pragma unroll
    for (int i = 0; i < 8; i++) {
        int m = bm + ((i < 4) ? (ty * 4 + i) : (64 + ty * 4 + i - 4));
        float4 o = make_float4(acc[i][0] + bs.x, acc[i][1] + bs.y,
                               acc[i][2] + bs.z, acc[i][3] + bs.w);
        size_t off = (size_t)m * ldC + bn + tx * 4;
        *reinterpret_cast<float4*>(&C[off]) = o;
        if (Chi) {
            uint32_t h0, h1, l0, l1;
            split4(o, h0, h1, l0, l1);
            *reinterpret_cast<uint2*>(&Chi[off]) = make_uint2(h0, h1);
            *reinterpret_cast<uint2*>(&Clo[off]) = make_uint2(l0, l1);
        }
    }
}

__global__ __launch_bounds__(256) void gemm_bias_kernel(
    const float* __restrict__ A, const float* __restrict__ W,
    const float* __restrict__ bias, float* __restrict__ C,
    int M, int N, int K)
{
    gemm_core_128x64(A, W, bias, C, N, K,
                     blockIdx.y * 128, blockIdx.x * 64, K, N, nullptr, nullptr);
}

__global__ __launch_bounds__(256) void qkv_kernel(
    const float* __restrict__ Q, const float* __restrict__ K,
    const float* __restrict__ V,
    const float* __restrict__ Wq, const float* __restrict__ Wk,
    const float* __restrict__ Wv,
    const float* __restrict__ bq, const float* __restrict__ bk,
    const float* __restrict__ bv,
    float* __restrict__ q, float* __restrict__ k, float* __restrict__ v,
    __nv_bfloat16* __restrict__ qh, __nv_bfloat16* __restrict__ ql,
    __nv_bfloat16* __restrict__ kh, __nv_bfloat16* __restrict__ kl)
{
    const float *A, *W, *bias;
    float* C;
    __nv_bfloat16 *Chi = nullptr, *Clo = nullptr;
    if (blockIdx.z == 0)      { A = Q; W = Wq; bias = bq; C = q; Chi = qh; Clo = ql; }
    else if (blockIdx.z == 1) { A = K; W = Wk; bias = bk; C = k; Chi = kh; Clo = kl; }
    else                      { A = V; W = Wv; bias = bv; C = v; }
    gemm_core_128x64(A, W, bias, C, HD, DM,
                     blockIdx.y * 128, blockIdx.x * 64, DM, HD, Chi, Clo);
}

// ---------------------------------------------------------------------------
// Tensor-core scores via mma.sync bf16 hi/lo (3 pairings), pre-split inputs,
// XOR-swizzled smem. __launch_bounds__(256,2) caps regs -> 2 CTAs/SM.
// ---------------------------------------------------------------------------
#define O_QH 0
#define O_QL (128*64)
#define O_KH (2*128*64)
#define O_KL (3*128*64)
#define SCORES_DYN (4*128*64*2)      // 65536 bytes

__global__ __launch_bounds__(256, 2) void scores_mma_kernel(
    const __nv_bfloat16* __restrict__ qh, const __nv_bfloat16* __restrict__ ql,
    const __nv_bfloat16* __restrict__ kh, const __nv_bfloat16* __restrict__ kl,
    const int* __restrict__ mask, float* __restrict__ attn,
    float* __restrict__ rowsum)
{
    extern __shared__ __align__(16) __nv_bfloat16 sm[];
    __shared__ int s_mask[128];

    const int tid = threadIdx.x, wid = tid >> 5, lane = tid & 31;
    const int bh = blockIdx.z, b = bh >> 1, h = bh & 1;
    const int i0 = blockIdx.y * 128, j0 = blockIdx.x * 128;
    const int wm = wid >> 1, wn = wid & 1;

    if (tid < 128) s_mask[tid] = mask[b * LL + j0 + tid];

    // stage pre-split bf16 tiles (swizzled): 4 buffers x 128 rows x 64
#pragma unroll
    for (int r = 0; r < 4; r++) {
        int idx = tid + r * 256;          // 1024 = 128 rows x 8 u4
        int m = idx >> 3, d8 = (idx & 7) * 8;
        int so = SWZ(m, d8);
        size_t qoff = (size_t)(b * LL + i0 + m) * HD + h * DK + d8;
        size_t koff = (size_t)(b * LL + j0 + m) * HD + h * DK + d8;
        *reinterpret_cast<uint4*>(&sm[O_QH + so]) =
            *reinterpret_cast<const uint4*>(&qh[qoff]);
        *reinterpret_cast<uint4*>(&sm[O_QL + so]) =
            *reinterpret_cast<const uint4*>(&ql[qoff]);
        *reinterpret_cast<uint4*>(&sm[O_KH + so]) =
            *reinterpret_cast<const uint4*>(&kh[koff]);
        *reinterpret_cast<uint4*>(&sm[O_KL + so]) =
            *reinterpret_cast<const uint4*>(&kl[koff]);
    }
    __syncthreads();

    float acc[2][8][4];
#pragma unroll
    for (int mt = 0; mt < 2; mt++)
#pragma unroll
        for (int nt = 0; nt < 8; nt++)
#pragma unroll
            for (int r = 0; r < 4; r++) acc[mt][nt][r] = 0.0f;

    const int gq = lane >> 2;
    const int qc = (lane & 3) * 2;

#pragma unroll
    for (int ks = 0; ks < 4; ks++) {
        const int kc = ks * 16 + qc;
        uint32_t ah[2][4], al[2][4];
#pragma unroll
        for (int mt = 0; mt < 2; mt++) {
            int gr = wm * 32 + mt * 16 + gq;
            ah[mt][0] = *reinterpret_cast<const uint32_t*>(&sm[O_QH + SWZ(gr, kc)]);
            ah[mt][1] = *reinterpret_cast<const uint32_t*>(&sm[O_QH + SWZ(gr + 8, kc)]);
            ah[mt][2] = *reinterpret_cast<const uint32_t*>(&sm[O_QH + SWZ(gr, kc + 8)]);
            ah[mt][3] = *reinterpret_cast<const uint32_t*>(&sm[O_QH + SWZ(gr + 8, kc + 8)]);
            al[mt][0] = *reinterpret_cast<const uint32_t*>(&sm[O_QL + SWZ(gr, kc)]);
            al[mt][1] = *reinterpret_cast<const uint32_t*>(&sm[O_QL + SWZ(gr + 8, kc)]);
            al[mt][2] = *reinterpret_cast<const uint32_t*>(&sm[O_QL + SWZ(gr, kc + 8)]);
            al[mt][3] = *reinterpret_cast<const uint32_t*>(&sm[O_QL + SWZ(gr + 8, kc + 8)]);
        }
#pragma unroll
        for (int nt = 0; nt < 8; nt++) {
            int jn = wn * 64 + nt * 8 + gq;
            uint32_t bh2[2], bl2[2];
            bh2[0] = *reinterpret_cast<const uint32_t*>(&sm[O_KH + SWZ(jn, kc)]);
            bh2[1] = *reinterpret_cast<const uint32_t*>(&sm[O_KH + SWZ(jn, kc + 8)]);
            bl2[0] = *reinterpret_cast<const uint32_t*>(&sm[O_KL + SWZ(jn, kc)]);
            bl2[1] = *reinterpret_cast<const uint32_t*>(&sm[O_KL + SWZ(jn, kc + 8)]);
#pragma unroll
            for (int mt = 0; mt < 2; mt++) {
                mma16816(acc[mt][nt], ah[mt], bh2);
                mma16816(acc[mt][nt], al[mt], bh2);
                mma16816(acc[mt][nt], ah[mt], bl2);
            }
        }
    }

#pragma unroll
    for (int mt = 0; mt < 2; mt++) {
        int r0 = wm * 32 + mt * 16 + gq;
        int r1 = r0 + 8;
        float rs0 = 0.0f, rs1 = 0.0f;
#pragma unroll
        for (int nt = 0; nt < 8; nt++) {
            int c = wn * 64 + nt * 8 + (lane & 3) * 2;
            int mk0 = s_mask[c], mk1 = s_mask[c + 1];
            float w0 = mk0 ? -10.0f : fast_tanh(acc[mt][nt][0] * 0.125f) * 10.0f;
            float w1 = mk1 ? -10.0f : fast_tanh(acc[mt][nt][1] * 0.125f) * 10.0f;
            float w2 = mk0 ? -10.0f : fast_tanh(acc[mt][nt][2] * 0.125f) * 10.0f;
            float w3 = mk1 ? -10.0f : fast_tanh(acc[mt][nt][3] * 0.125f) * 10.0f;
            *reinterpret_cast<float2*>(
                &attn[((size_t)bh * LL + i0 + r0) * LL + j0 + c]) = make_float2(w0, w1);
            *reinterpret_cast<float2*>(
                &attn[((size_t)bh * LL + i0 + r1) * LL + j0 + c]) = make_float2(w2, w3);
            rs0 += __expf(w0) + __expf(w1);
            rs1 += __expf(w2) + __expf(w3);
        }
        rs0 += __shfl_xor_sync(0xffffffffu, rs0, 1);
        rs0 += __shfl_xor_sync(0xffffffffu, rs0, 2);
        rs1 += __shfl_xor_sync(0xffffffffu, rs1, 1);
        rs1 += __shfl_xor_sync(0xffffffffu, rs1, 2);
        if ((lane & 3) == 0) {
            atomicAdd(&rowsum[bh * LL + i0 + r0], rs0);
            atomicAdd(&rowsum[bh * LL + i0 + r1], rs1);
        }
    }
}

// ---------------------------------------------------------------------------
// av via mma.sync, double-buffered + register-prefetch pipeline. (R15-proven)
// ---------------------------------------------------------------------------
#define AV_STAGE 24576
#define AV_AH 0
#define AV_AL 8192
#define AV_BH 16384
#define AV_BL 20480
#define AV_DYN (2*AV_STAGE*2 + 512)

__global__ __launch_bounds__(256) void av_mma_kernel(
    float* __restrict__ attn,
    const __nv_bfloat16* __restrict__ vth, const __nv_bfloat16* __restrict__ vtl,
    const float* __restrict__ lse, float* __restrict__ oh)
{
    extern __shared__ __align__(16) __nv_bfloat16 sm[];
    float* lse_s = reinterpret_cast<float*>(sm + 2 * AV_STAGE);

    const int tid = threadIdx.x, wid = tid >> 5, lane = tid & 31;
    const int bh = blockIdx.y, b = bh >> 1, h = bh & 1;
    const int i0 = blockIdx.x * 128;
    const int gq = lane >> 2, qc = (lane & 3) * 2;

    if (tid < 128) lse_s[tid] = lse[bh * LL + i0 + tid];
    __syncthreads();

    float acc[8][4];
#pragma unroll
    for (int nt = 0; nt < 8; nt++)
#pragma unroll
        for (int r = 0; r < 4; r++) acc[nt][r] = 0.0f;

    float4 pa[8];
    uint4  pbh[2], pbl[2];

    auto issue_loads = [&](int k0) {
#pragma unroll
        for (int r = 0; r < 8; r++) {
            int idx = tid + r * 256;
            int i = idx >> 4, j4 = (idx & 15) * 4;
            pa[r] = *reinterpret_cast<const float4*>(
                &attn[((size_t)bh * LL + i0 + i) * LL + k0 + j4]);
        }
#pragma unroll
        for (int r = 0; r < 2; r++) {
            int idx = tid + r * 256;
            int d = idx >> 3, j8 = (idx & 7) * 8;
            size_t off = (size_t)(bh * DK + d) * LL + k0 + j8;
            pbh[r] = *reinterpret_cast<const uint4*>(&vth[off]);
            pbl[r] = *reinterpret_cast<const uint4*>(&vtl[off]);
        }
    };
    auto convert_store = [&](int k0, int buf) {
        int base = buf * AV_STAGE;
#pragma unroll
        for (int r = 0; r < 8; r++) {
            int idx = tid + r * 256;
            int i = idx >> 4, j4 = (idx & 15) * 4;
            float4 t = pa[r];
            float l = lse_s[i];
            t.x -= l; t.y -= l; t.z -= l; t.w -= l;
            *reinterpret_cast<float4*>(
                &attn[((size_t)bh * LL + i0 + i) * LL + k0 + j4]) = t;
            uint32_t h0, h1, l0, l1;
            split4(t, h0, h1, l0, l1);
            int so = SWZ(i, j4);
            *reinterpret_cast<uint2*>(&sm[base + AV_AH + so]) = make_uint2(h0, h1);
            *reinterpret_cast<uint2*>(&sm[base + AV_AL + so]) = make_uint2(l0, l1);
        }
#pragma unroll
        for (int r = 0; r < 2; r++) {
            int idx = tid + r * 256;
            int d = idx >> 3, j8 = (idx & 7) * 8;
            int so = SWZ(d, j8);
            *reinterpret_cast<uint4*>(&sm[base + AV_BH + so]) = pbh[r];
            *reinterpret_cast<uint4*>(&sm[base + AV_BL + so]) = pbl[r];
        }
    };

    issue_loads(0);
    convert_store(0, 0);
    __syncthreads();

    for (int t = 0; t < 32; t++) {
        int buf = t & 1;
        int base = buf * AV_STAGE;
        if (t < 31) issue_loads((t + 1) * 64);

#pragma unroll
        for (int ks = 0; ks < 4; ks++) {
            const int kc = ks * 16 + qc;
            int gr = wid * 16 + gq;
            uint32_t ah[4], al[4];
            ah[0] = *reinterpret_cast<const uint32_t*>(&sm[base + AV_AH + SWZ(gr, kc)]);
            ah[1] = *reinterpret_cast<const uint32_t*>(&sm[base + AV_AH + SWZ(gr + 8, kc)]);
            ah[2] = *reinterpret_cast<const uint32_t*>(&sm[base + AV_AH + SWZ(gr, kc + 8)]);
            ah[3] = *reinterpret_cast<const uint32_t*>(&sm[base + AV_AH + SWZ(gr + 8, kc + 8)]);
            al[0] = *reinterpret_cast<const uint32_t*>(&sm[base + AV_AL + SWZ(gr, kc)]);
            al[1] = *reinterpret_cast<const uint32_t*>(&sm[base + AV_AL + SWZ(gr + 8, kc)]);
            al[2] = *reinterpret_cast<const uint32_t*>(&sm[base + AV_AL + SWZ(gr, kc + 8)]);
            al[3] = *reinterpret_cast<const uint32_t*>(&sm[base + AV_AL + SWZ(gr + 8, kc + 8)]);
#pragma unroll
            for (int nt = 0; nt < 8; nt++) {
                int dn = nt * 8 + gq;
                uint32_t bh2[2], bl2[2];
                bh2[0] = *reinterpret_cast<const uint32_t*>(&sm[base + AV_BH + SWZ(dn, kc)]);
                bh2[1] = *reinterpret_cast<const uint32_t*>(&sm[base + AV_BH + SWZ(dn, kc + 8)]);
                bl2[0] = *reinterpret_cast<const uint32_t*>(&sm[base + AV_BL + SWZ(dn, kc)]);
                bl2[1] = *reinterpret_cast<const uint32_t*>(&sm[base + AV_BL + SWZ(dn, kc + 8)]);
                mma16816(acc[nt], ah, bh2);
                mma16816(acc[nt], al, bh2);
                mma16816(acc[nt], ah, bl2);
            }
        }

        if (t < 31) convert_store((t + 1) * 64, 1 - buf);
        __syncthreads();
    }

    int r0 = i0 + wid * 16 + gq;
    int r1 = r0 + 8;
#pragma unroll
    for (int nt = 0; nt < 8; nt++) {
        int c = nt * 8 + (lane & 3) * 2;
        *reinterpret_cast<float2*>(
            &oh[(size_t)(b * LL + r0) * HD + h * DK + c]) =
            make_float2(acc[nt][0], acc[nt][1]);
        *reinterpret_cast<float2*>(
            &oh[(size_t)(b * LL + r1) * HD + h * DK + c]) =
            make_float2(acc[nt][2], acc[nt][3]);
    }
}

// ---------------------------------------------------------------------------
extern "C" void kernel_launch(void* const* d_in, const int* in_sizes, int n_in,
                              void* d_out, int out_size)
{
    const float* Q  = (const float*)d_in[0];
    const float* K  = (const float*)d_in[1];
    const float* V  = (const float*)d_in[2];
    const int*   mask = (const int*)d_in[3];
    const float* Wq = (const float*)d_in[4];
    const float* bq = (const float*)d_in[5];
    const float* Wk = (const float*)d_in[6];
    const float* bk = (const float*)d_in[7];
    const float* Wv = (const float*)d_in[8];
    const float* bv = (const float*)d_in[9];
    const float* Wo = (const float*)d_in[10];
    const float* bo = (const float*)d_in[11];

    float* out  = (float*)d_out;          // [B, Lq, 512]
    float* attn = out + OUT0;             // [B, H, Lq, Lk]

    float *q, *k, *v, *oh, *rs;
    __nv_bfloat16 *qh, *ql, *kh, *kl, *vth, *vtl;
    cudaGetSymbolAddress((void**)&q,  g_q);
    cudaGetSymbolAddress((void**)&k,  g_k);
    cudaGetSymbolAddress((void**)&v,  g_v);
    cudaGetSymbolAddress((void**)&oh, g_oh);
    cudaGetSymbolAddress((void**)&rs, g_rowsum);
    cudaGetSymbolAddress((void**)&qh, g_qh);
    cudaGetSymbolAddress((void**)&ql, g_ql);
    cudaGetSymbolAddress((void**)&kh, g_kh);
    cudaGetSymbolAddress((void**)&kl, g_kl);
    cudaGetSymbolAddress((void**)&vth, g_vth);
    cudaGetSymbolAddress((void**)&vtl, g_vtl);

    const int M = BB * LL;                // 8192
    cudaFuncSetAttribute(scores_mma_kernel,
                         cudaFuncAttributeMaxDynamicSharedMemorySize, SCORES_DYN);
    cudaFuncSetAttribute(av_mma_kernel,
                         cudaFuncAttributeMaxDynamicSharedMemorySize, AV_DYN);

    // 0) zero the rowsum accumulator
    zero_rowsum_kernel<<<NROWS / 256, 256>>>(rs);

    // 1) fused projections (+ bf16 hi/lo emission for q,k)
    dim3 gp(HD / 64, M / 128, 3);
    qkv_kernel<<<gp, 256>>>(Q, K, V, Wq, Wk, Wv, bq, bk, bv,
                            q, k, v, qh, ql, kh, kl);

    // 1b) transpose+split v -> vt (bf16 hi/lo)
    dim3 gv(LL / 128, BB * NH);
    vt_convert_kernel<<<gv, 256>>>(v, vth, vtl);

    // 2) tensor-core scores + tanh clip + mask -> attn (raw) + rowsum atomics
    dim3 gs(LL / 128, LL / 128, BB * NH);
    scores_mma_kernel<<<gs, 256, SCORES_DYN>>>(qh, ql, kh, kl, mask, attn, rs);

    // 3) rowsum -> lse
    lse_kernel<<<NROWS / 256, 256>>>(rs);

    // 4) attn = s - lse (written back) ; oh = attn @ v (tensor, pipelined)
    dim3 ga(LL / 128, BB * NH);
    av_mma_kernel<<<ga, 256, AV_DYN>>>(attn, vth, vtl, rs, oh);

    // 5) out = oh @ Wo + bo : [8192,128] @ [128,512]
    dim3 go(DM / 64, M / 128);
    gemm_bias_kernel<<<go, 256>>>(oh, Wo, bo, out, M, DM, HD);
}